// round 1
// baseline (speedup 1.0000x reference)
#include <cuda_runtime.h>
#include <cuda_bf16.h>

#define D 256
#define MAX_NODES 100000

// Scratch for x = inputs @ W  (100000*256 floats = 102.4 MB)
static __device__ float g_x[(size_t)MAX_NODES * D];

// ---------------------------------------------------------------------------
// GEMM: C[M,256] = A[M,256] @ B[256,256], fp32
// BM=64, BN=64, BK=16, 256 threads, 4x4 microtile per thread
// ---------------------------------------------------------------------------
__global__ __launch_bounds__(256) void gemm_kernel(
    const float* __restrict__ A, const float* __restrict__ B,
    float* __restrict__ C, int M)
{
    __shared__ float As[16][65];   // [k][m], padded
    __shared__ float Bs[16][64];   // [k][n]

    const int tid = threadIdx.x;
    const int tx = tid & 15;       // col group
    const int ty = tid >> 4;       // row group
    const int block_row = blockIdx.x * 64;
    const int block_col = blockIdx.y * 64;

    float acc[4][4] = {};

    for (int k0 = 0; k0 < 256; k0 += 16) {
        // Load A tile 64x16 (transposed into As[k][m])
        {
            int r = tid >> 2;            // 0..63
            int c = (tid & 3) * 4;       // 0,4,8,12
            int gr = block_row + r;
            float4 v = make_float4(0.f, 0.f, 0.f, 0.f);
            if (gr < M)
                v = *reinterpret_cast<const float4*>(&A[(size_t)gr * 256 + k0 + c]);
            As[c + 0][r] = v.x;
            As[c + 1][r] = v.y;
            As[c + 2][r] = v.z;
            As[c + 3][r] = v.w;
        }
        // Load B tile 16x64
        {
            int r = tid >> 4;            // 0..15
            int c = (tid & 15) * 4;      // 0..60
            *reinterpret_cast<float4*>(&Bs[r][c]) =
                *reinterpret_cast<const float4*>(&B[(size_t)(k0 + r) * 256 + block_col + c]);
        }
        __syncthreads();

#pragma unroll
        for (int k = 0; k < 16; k++) {
            float a[4], b[4];
#pragma unroll
            for (int i = 0; i < 4; i++) a[i] = As[k][ty * 4 + i];
#pragma unroll
            for (int j = 0; j < 4; j++) b[j] = Bs[k][tx * 4 + j];
#pragma unroll
            for (int i = 0; i < 4; i++)
#pragma unroll
                for (int j = 0; j < 4; j++)
                    acc[i][j] += a[i] * b[j];
        }
        __syncthreads();
    }

#pragma unroll
    for (int i = 0; i < 4; i++) {
        int gr = block_row + ty * 4 + i;
        if (gr < M) {
            float4 v = make_float4(acc[i][0], acc[i][1], acc[i][2], acc[i][3]);
            *reinterpret_cast<float4*>(&C[(size_t)gr * 256 + block_col + tx * 4]) = v;
        }
    }
}

// ---------------------------------------------------------------------------
// Zero-init output
// ---------------------------------------------------------------------------
__global__ __launch_bounds__(256) void zero_kernel(float4* __restrict__ p, int n4)
{
    int i = blockIdx.x * blockDim.x + threadIdx.x;
    if (i < n4) p[i] = make_float4(0.f, 0.f, 0.f, 0.f);
}

// ---------------------------------------------------------------------------
// SpMM scatter: one warp per edge.
// Each lane handles 8 consecutive floats (2x float4) of the 256-wide row.
// Uses red.global.add.v4.f32 (no-return vector reduction, sm_90+).
// ---------------------------------------------------------------------------
__global__ __launch_bounds__(256) void spmm_kernel(
    const int* __restrict__ esrc, const int* __restrict__ edst,
    const float* __restrict__ evals, const float* __restrict__ x,
    float* __restrict__ out, int E)
{
    int warp = (blockIdx.x * blockDim.x + threadIdx.x) >> 5;
    int lane = threadIdx.x & 31;
    if (warp >= E) return;

    int s = esrc[warp];
    int d = edst[warp];
    float v = evals[warp];

    const float4* xr = reinterpret_cast<const float4*>(x + (size_t)s * D) + lane * 2;
    float4 a = __ldg(xr);
    float4 b = __ldg(xr + 1);
    a.x *= v; a.y *= v; a.z *= v; a.w *= v;
    b.x *= v; b.y *= v; b.z *= v; b.w *= v;

    float* o = out + (size_t)d * D + lane * 8;
    asm volatile("red.global.add.v4.f32 [%0], {%1,%2,%3,%4};"
                 :: "l"(o), "f"(a.x), "f"(a.y), "f"(a.z), "f"(a.w) : "memory");
    asm volatile("red.global.add.v4.f32 [%0], {%1,%2,%3,%4};"
                 :: "l"(o + 4), "f"(b.x), "f"(b.y), "f"(b.z), "f"(b.w) : "memory");
}

// ---------------------------------------------------------------------------
// ReLU epilogue
// ---------------------------------------------------------------------------
__global__ __launch_bounds__(256) void relu_kernel(float4* __restrict__ p, int n4)
{
    int i = blockIdx.x * blockDim.x + threadIdx.x;
    if (i < n4) {
        float4 v = p[i];
        v.x = fmaxf(v.x, 0.f);
        v.y = fmaxf(v.y, 0.f);
        v.z = fmaxf(v.z, 0.f);
        v.w = fmaxf(v.w, 0.f);
        p[i] = v;
    }
}

// ---------------------------------------------------------------------------
// Launcher
// ---------------------------------------------------------------------------
extern "C" void kernel_launch(void* const* d_in, const int* in_sizes, int n_in,
                              void* d_out, int out_size)
{
    const float* inputs = (const float*)d_in[0];
    const float* W      = (const float*)d_in[1];
    const int*   esrc   = (const int*)  d_in[2];
    const int*   edst   = (const int*)  d_in[3];
    const float* evals  = (const float*)d_in[4];
    float*       out    = (float*)d_out;

    const int M = in_sizes[0] / D;     // 100000
    const int E = in_sizes[2];         // 3200000

    float* x = nullptr;
    cudaGetSymbolAddress((void**)&x, g_x);   // address query only; not a stream op

    // 1. zero the output (poisoned by harness)
    {
        int n4 = out_size / 4;
        int blocks = (n4 + 255) / 256;
        zero_kernel<<<blocks, 256>>>((float4*)out, n4);
    }

    // 2. x = inputs @ W
    {
        dim3 grid((M + 63) / 64, D / 64);
        gemm_kernel<<<grid, 256>>>(inputs, W, x, M);
    }

    // 3. scatter-add messages (1 warp per edge)
    {
        long long total_warps = E;
        long long total_threads = total_warps * 32;
        int blocks = (int)((total_threads + 255) / 256);
        spmm_kernel<<<blocks, 256>>>(esrc, edst, evals, x, out, E);
    }

    // 4. ReLU
    {
        int n4 = out_size / 4;
        int blocks = (n4 + 255) / 256;
        relu_kernel<<<blocks, 256>>>((float4*)out, n4);
    }
}

// round 2
// speedup vs baseline: 2.2404x; 2.2404x over previous
#include <cuda_runtime.h>
#include <cuda_bf16.h>

#define D 256
#define MAX_NODES 100000
#define MAX_EDGES 3200000
#define SCAN_BLK 1024

// ---- device scratch (static: allocation rules) ----
static __device__ float g_x[(size_t)MAX_NODES * D];     // inputs @ W
static __device__ int   g_cnt[MAX_NODES];               // per-dst degree
static __device__ int   g_off[MAX_NODES];               // exclusive prefix
static __device__ int   g_cur[MAX_NODES];               // scatter cursor
static __device__ int   g_bsum[(MAX_NODES + SCAN_BLK - 1) / SCAN_BLK + 1];
static __device__ int   g_ssrc[MAX_EDGES];              // src sorted by dst
static __device__ float g_sval[MAX_EDGES];              // val sorted by dst

// ---------------------------------------------------------------------------
// CSR build: zero counts -> histogram -> scan (3 kernels) -> scatter
// ---------------------------------------------------------------------------
__global__ __launch_bounds__(256) void zero_cnt_kernel(int* __restrict__ cnt, int n)
{
    int i = blockIdx.x * blockDim.x + threadIdx.x;
    if (i < n) cnt[i] = 0;
}

__global__ __launch_bounds__(256) void hist_kernel(
    const int* __restrict__ edst, int* __restrict__ cnt, int E)
{
    int i = blockIdx.x * blockDim.x + threadIdx.x;
    if (i < E) atomicAdd(&cnt[edst[i]], 1);
}

// Block-local exclusive scan (Hillis-Steele), emits per-block totals
__global__ __launch_bounds__(SCAN_BLK) void scan1_kernel(
    const int* __restrict__ cnt, int* __restrict__ off, int* __restrict__ bsum, int n)
{
    __shared__ int s[SCAN_BLK];
    int tid = threadIdx.x;
    int i = blockIdx.x * SCAN_BLK + tid;
    int v = (i < n) ? cnt[i] : 0;
    s[tid] = v;
    __syncthreads();
#pragma unroll
    for (int d = 1; d < SCAN_BLK; d <<= 1) {
        int t = (tid >= d) ? s[tid - d] : 0;
        __syncthreads();
        s[tid] += t;
        __syncthreads();
    }
    if (i < n) off[i] = s[tid] - v;                 // exclusive
    if (tid == SCAN_BLK - 1) bsum[blockIdx.x] = s[tid];
}

// Scan the block sums (single block; nblocks <= SCAN_BLK)
__global__ __launch_bounds__(SCAN_BLK) void scan2_kernel(int* __restrict__ bsum, int nb)
{
    __shared__ int s[SCAN_BLK];
    int tid = threadIdx.x;
    int v = (tid < nb) ? bsum[tid] : 0;
    s[tid] = v;
    __syncthreads();
#pragma unroll
    for (int d = 1; d < SCAN_BLK; d <<= 1) {
        int t = (tid >= d) ? s[tid - d] : 0;
        __syncthreads();
        s[tid] += t;
        __syncthreads();
    }
    if (tid < nb) bsum[tid] = s[tid] - v;           // exclusive
}

// Add block offsets; initialize scatter cursor
__global__ __launch_bounds__(256) void scan3_kernel(
    int* __restrict__ off, const int* __restrict__ bsum, int* __restrict__ cur, int n)
{
    int i = blockIdx.x * blockDim.x + threadIdx.x;
    if (i < n) {
        int o = off[i] + bsum[i / SCAN_BLK];
        off[i] = o;
        cur[i] = o;
    }
}

__global__ __launch_bounds__(256) void scatter_kernel(
    const int* __restrict__ esrc, const int* __restrict__ edst,
    const float* __restrict__ evals, int* __restrict__ cur,
    int* __restrict__ ssrc, float* __restrict__ sval, int E)
{
    int i = blockIdx.x * blockDim.x + threadIdx.x;
    if (i < E) {
        int d = edst[i];
        int pos = atomicAdd(&cur[d], 1);
        ssrc[pos] = esrc[i];
        sval[pos] = evals[i];
    }
}

// ---------------------------------------------------------------------------
// GEMM: C[M,256] = A[M,256] @ B[256,256]
// BM=128, BN=128, BK=16, 256 threads, 8x8 microtile
// ---------------------------------------------------------------------------
__global__ __launch_bounds__(256, 2) void gemm_kernel(
    const float* __restrict__ A, const float* __restrict__ B,
    float* __restrict__ C, int M)
{
    __shared__ float As[16][128];   // [k][m]
    __shared__ float Bs[16][128];   // [k][n]

    const int tid = threadIdx.x;
    const int tx = tid & 15;        // n group
    const int ty = tid >> 4;        // m group
    const int row0 = blockIdx.x * 128;
    const int col0 = blockIdx.y * 128;

    float acc[8][8] = {};

    for (int k0 = 0; k0 < 256; k0 += 16) {
        // A tile: 128x16 -> As[k][m]; 512 float4, 2 per thread
#pragma unroll
        for (int i = 0; i < 2; i++) {
            int f = tid * 2 + i;
            int r = f >> 2;
            int c = (f & 3) * 4;
            int gr = row0 + r;
            float4 v = make_float4(0.f, 0.f, 0.f, 0.f);
            if (gr < M)
                v = *reinterpret_cast<const float4*>(&A[(size_t)gr * 256 + k0 + c]);
            As[c + 0][r] = v.x;
            As[c + 1][r] = v.y;
            As[c + 2][r] = v.z;
            As[c + 3][r] = v.w;
        }
        // B tile: 16x128; 512 float4, 2 per thread
#pragma unroll
        for (int i = 0; i < 2; i++) {
            int f = tid * 2 + i;
            int r = f >> 5;
            int c = (f & 31) * 4;
            *reinterpret_cast<float4*>(&Bs[r][c]) =
                *reinterpret_cast<const float4*>(&B[(size_t)(k0 + r) * 256 + col0 + c]);
        }
        __syncthreads();

#pragma unroll
        for (int k = 0; k < 16; k++) {
            float a[8], b[8];
            *reinterpret_cast<float4*>(&a[0]) = *reinterpret_cast<float4*>(&As[k][ty * 8]);
            *reinterpret_cast<float4*>(&a[4]) = *reinterpret_cast<float4*>(&As[k][ty * 8 + 4]);
            *reinterpret_cast<float4*>(&b[0]) = *reinterpret_cast<float4*>(&Bs[k][tx * 8]);
            *reinterpret_cast<float4*>(&b[4]) = *reinterpret_cast<float4*>(&Bs[k][tx * 8 + 4]);
#pragma unroll
            for (int i = 0; i < 8; i++)
#pragma unroll
                for (int j = 0; j < 8; j++)
                    acc[i][j] += a[i] * b[j];
        }
        __syncthreads();
    }

#pragma unroll
    for (int i = 0; i < 8; i++) {
        int gr = row0 + ty * 8 + i;
        if (gr < M) {
            *reinterpret_cast<float4*>(&C[(size_t)gr * 256 + col0 + tx * 8]) =
                make_float4(acc[i][0], acc[i][1], acc[i][2], acc[i][3]);
            *reinterpret_cast<float4*>(&C[(size_t)gr * 256 + col0 + tx * 8 + 4]) =
                make_float4(acc[i][4], acc[i][5], acc[i][6], acc[i][7]);
        }
    }
}

// ---------------------------------------------------------------------------
// SpMM by destination (CSR): one warp per node, accumulate in registers,
// fused ReLU + single store (no zero-init, no atomics on out).
// ---------------------------------------------------------------------------
__global__ __launch_bounds__(256) void spmm_csr_kernel(
    const int* __restrict__ off, const int* __restrict__ cnt,
    const int* __restrict__ ssrc, const float* __restrict__ sval,
    const float* __restrict__ x, float* __restrict__ out, int N)
{
    int warp = (blockIdx.x * blockDim.x + threadIdx.x) >> 5;
    int lane = threadIdx.x & 31;
    if (warp >= N) return;

    int beg = off[warp];
    int end = beg + cnt[warp];

    float4 acc0 = make_float4(0.f, 0.f, 0.f, 0.f);
    float4 acc1 = make_float4(0.f, 0.f, 0.f, 0.f);

    int e = beg;
    // 2-edge unroll for memory-level parallelism
    for (; e + 2 <= end; e += 2) {
        int s0 = ssrc[e],   s1 = ssrc[e + 1];
        float v0 = sval[e], v1 = sval[e + 1];
        const float4* p0 = reinterpret_cast<const float4*>(x + (size_t)s0 * D) + lane * 2;
        const float4* p1 = reinterpret_cast<const float4*>(x + (size_t)s1 * D) + lane * 2;
        float4 a0 = __ldg(p0), b0 = __ldg(p0 + 1);
        float4 a1 = __ldg(p1), b1 = __ldg(p1 + 1);
        acc0.x = fmaf(v0, a0.x, acc0.x); acc0.y = fmaf(v0, a0.y, acc0.y);
        acc0.z = fmaf(v0, a0.z, acc0.z); acc0.w = fmaf(v0, a0.w, acc0.w);
        acc1.x = fmaf(v0, b0.x, acc1.x); acc1.y = fmaf(v0, b0.y, acc1.y);
        acc1.z = fmaf(v0, b0.z, acc1.z); acc1.w = fmaf(v0, b0.w, acc1.w);
        acc0.x = fmaf(v1, a1.x, acc0.x); acc0.y = fmaf(v1, a1.y, acc0.y);
        acc0.z = fmaf(v1, a1.z, acc0.z); acc0.w = fmaf(v1, a1.w, acc0.w);
        acc1.x = fmaf(v1, b1.x, acc1.x); acc1.y = fmaf(v1, b1.y, acc1.y);
        acc1.z = fmaf(v1, b1.z, acc1.z); acc1.w = fmaf(v1, b1.w, acc1.w);
    }
    if (e < end) {
        int s0 = ssrc[e];
        float v0 = sval[e];
        const float4* p0 = reinterpret_cast<const float4*>(x + (size_t)s0 * D) + lane * 2;
        float4 a0 = __ldg(p0), b0 = __ldg(p0 + 1);
        acc0.x = fmaf(v0, a0.x, acc0.x); acc0.y = fmaf(v0, a0.y, acc0.y);
        acc0.z = fmaf(v0, a0.z, acc0.z); acc0.w = fmaf(v0, a0.w, acc0.w);
        acc1.x = fmaf(v0, b0.x, acc1.x); acc1.y = fmaf(v0, b0.y, acc1.y);
        acc1.z = fmaf(v0, b0.z, acc1.z); acc1.w = fmaf(v0, b0.w, acc1.w);
    }

    // fused ReLU + single store
    acc0.x = fmaxf(acc0.x, 0.f); acc0.y = fmaxf(acc0.y, 0.f);
    acc0.z = fmaxf(acc0.z, 0.f); acc0.w = fmaxf(acc0.w, 0.f);
    acc1.x = fmaxf(acc1.x, 0.f); acc1.y = fmaxf(acc1.y, 0.f);
    acc1.z = fmaxf(acc1.z, 0.f); acc1.w = fmaxf(acc1.w, 0.f);

    float4* o = reinterpret_cast<float4*>(out + (size_t)warp * D) + lane * 2;
    o[0] = acc0;
    o[1] = acc1;
}

// ---------------------------------------------------------------------------
// Launcher
// ---------------------------------------------------------------------------
extern "C" void kernel_launch(void* const* d_in, const int* in_sizes, int n_in,
                              void* d_out, int out_size)
{
    const float* inputs = (const float*)d_in[0];
    const float* W      = (const float*)d_in[1];
    const int*   esrc   = (const int*)  d_in[2];
    const int*   edst   = (const int*)  d_in[3];
    const float* evals  = (const float*)d_in[4];
    float*       out    = (float*)d_out;

    const int M = in_sizes[0] / D;     // 100000
    const int E = in_sizes[2];         // 3200000

    float *x, *sval;
    int *cnt, *off, *cur, *bsum, *ssrc;
    cudaGetSymbolAddress((void**)&x,    g_x);
    cudaGetSymbolAddress((void**)&cnt,  g_cnt);
    cudaGetSymbolAddress((void**)&off,  g_off);
    cudaGetSymbolAddress((void**)&cur,  g_cur);
    cudaGetSymbolAddress((void**)&bsum, g_bsum);
    cudaGetSymbolAddress((void**)&ssrc, g_ssrc);
    cudaGetSymbolAddress((void**)&sval, g_sval);

    const int nblocks_scan = (M + SCAN_BLK - 1) / SCAN_BLK;

    // ---- CSR build ----
    zero_cnt_kernel<<<(M + 255) / 256, 256>>>(cnt, M);
    hist_kernel<<<(E + 255) / 256, 256>>>(edst, cnt, E);
    scan1_kernel<<<nblocks_scan, SCAN_BLK>>>(cnt, off, bsum, M);
    scan2_kernel<<<1, SCAN_BLK>>>(bsum, nblocks_scan);
    scan3_kernel<<<(M + 255) / 256, 256>>>(off, bsum, cur, M);
    scatter_kernel<<<(E + 255) / 256, 256>>>(esrc, edst, evals, cur, ssrc, sval, E);

    // ---- x = inputs @ W ----
    {
        dim3 grid((M + 127) / 128, D / 128);
        gemm_kernel<<<grid, 256>>>(inputs, W, x, M);
    }

    // ---- SpMM-CSR + ReLU (writes every output row exactly once) ----
    {
        long long threads = (long long)M * 32;
        int blocks = (int)((threads + 255) / 256);
        spmm_csr_kernel<<<blocks, 256>>>(off, cnt, ssrc, sval, x, out, M);
    }
}

// round 3
// speedup vs baseline: 3.3765x; 1.5071x over previous
#include <cuda_runtime.h>
#include <cuda_bf16.h>
#include <cstdint>

#define D 256
#define MAX_NODES 100000
#define MAX_EDGES 3200000
#define SCAN_BLK 1024

// ---- device scratch (static: allocation rules) ----
static __device__ float g_x[(size_t)MAX_NODES * D];     // inputs @ W
static __device__ int   g_cnt[MAX_NODES];               // per-dst degree
static __device__ int   g_off[MAX_NODES];               // exclusive prefix
static __device__ int   g_cur[MAX_NODES];               // scatter cursor
static __device__ int   g_bsum[(MAX_NODES + SCAN_BLK - 1) / SCAN_BLK + 1];
static __device__ int   g_ssrc[MAX_EDGES];              // src sorted by dst
static __device__ float g_sval[MAX_EDGES];              // val sorted by dst

// ---------------------------------------------------------------------------
// CSR build kernels
// ---------------------------------------------------------------------------
__global__ __launch_bounds__(256) void zero_cnt_kernel(int* __restrict__ cnt, int n)
{
    int i = blockIdx.x * blockDim.x + threadIdx.x;
    if (i < n) cnt[i] = 0;
}

__global__ __launch_bounds__(256) void hist_kernel(
    const int* __restrict__ edst, int* __restrict__ cnt, int E)
{
    int i = blockIdx.x * blockDim.x + threadIdx.x;
    if (i < E) atomicAdd(&cnt[edst[i]], 1);
}

__global__ __launch_bounds__(SCAN_BLK) void scan1_kernel(
    const int* __restrict__ cnt, int* __restrict__ off, int* __restrict__ bsum, int n)
{
    __shared__ int s[SCAN_BLK];
    int tid = threadIdx.x;
    int i = blockIdx.x * SCAN_BLK + tid;
    int v = (i < n) ? cnt[i] : 0;
    s[tid] = v;
    __syncthreads();
#pragma unroll
    for (int d = 1; d < SCAN_BLK; d <<= 1) {
        int t = (tid >= d) ? s[tid - d] : 0;
        __syncthreads();
        s[tid] += t;
        __syncthreads();
    }
    if (i < n) off[i] = s[tid] - v;
    if (tid == SCAN_BLK - 1) bsum[blockIdx.x] = s[tid];
}

__global__ __launch_bounds__(SCAN_BLK) void scan2_kernel(int* __restrict__ bsum, int nb)
{
    __shared__ int s[SCAN_BLK];
    int tid = threadIdx.x;
    int v = (tid < nb) ? bsum[tid] : 0;
    s[tid] = v;
    __syncthreads();
#pragma unroll
    for (int d = 1; d < SCAN_BLK; d <<= 1) {
        int t = (tid >= d) ? s[tid - d] : 0;
        __syncthreads();
        s[tid] += t;
        __syncthreads();
    }
    if (tid < nb) bsum[tid] = s[tid] - v;
}

__global__ __launch_bounds__(256) void scan3_kernel(
    int* __restrict__ off, const int* __restrict__ bsum, int* __restrict__ cur, int n)
{
    int i = blockIdx.x * blockDim.x + threadIdx.x;
    if (i < n) {
        int o = off[i] + bsum[i / SCAN_BLK];
        off[i] = o;
        cur[i] = o;
    }
}

__global__ __launch_bounds__(256) void scatter_kernel(
    const int* __restrict__ esrc, const int* __restrict__ edst,
    const float* __restrict__ evals, int* __restrict__ cur,
    int* __restrict__ ssrc, float* __restrict__ sval, int E)
{
    int i = blockIdx.x * blockDim.x + threadIdx.x;
    if (i < E) {
        int d = edst[i];
        int pos = atomicAdd(&cur[d], 1);
        ssrc[pos] = esrc[i];
        sval[pos] = evals[i];
    }
}

// ---------------------------------------------------------------------------
// tf32 tensor-core GEMM: C[M,256] = A[M,256] @ B[256,256]
// CTA 128x128, 8 warps (4x2), warp tile 32x64, BK=16, cp.async double buffer
// mma.sync.aligned.m16n8k8.row.col.f32.tf32.tf32.f32
// ---------------------------------------------------------------------------
#define BM 128
#define BN 128
#define BK 16
#define S_A 20    // As row stride (floats): conflict-free for frag loads
#define S_B 136   // Bs row stride (floats): conflict-free for frag loads

__device__ __forceinline__ void cp_async16(uint32_t dst, const void* src, bool valid)
{
    int sz = valid ? 16 : 0;
    asm volatile("cp.async.ca.shared.global [%0], [%1], 16, %2;\n"
                 :: "r"(dst), "l"(src), "r"(sz));
}

__device__ __forceinline__ uint32_t f2tf32(float f)
{
    uint32_t u;
    asm("cvt.rna.tf32.f32 %0, %1;" : "=r"(u) : "f"(f));
    return u;
}

__global__ __launch_bounds__(256, 2) void gemm_tf32_kernel(
    const float* __restrict__ A, const float* __restrict__ B,
    float* __restrict__ C, int M)
{
    __shared__ float As[2][BM * S_A];
    __shared__ float Bs[2][BK * S_B];

    const int tid = threadIdx.x;
    const int lane = tid & 31;
    const int wid = tid >> 5;
    const int g = lane >> 2;       // groupID (0..7)
    const int t = lane & 3;        // thread-in-group (0..3)
    const int warp_m = (wid >> 1) * 32;
    const int warp_n = (wid & 1) * 64;
    const int row0 = blockIdx.x * BM;
    const int col0 = blockIdx.y * BN;

    float c[2][8][4];
#pragma unroll
    for (int i = 0; i < 2; i++)
#pragma unroll
        for (int j = 0; j < 8; j++)
#pragma unroll
            for (int k = 0; k < 4; k++) c[i][j][k] = 0.f;

    uint32_t sA[2], sB[2];
    sA[0] = (uint32_t)__cvta_generic_to_shared(&As[0][0]);
    sA[1] = (uint32_t)__cvta_generic_to_shared(&As[1][0]);
    sB[0] = (uint32_t)__cvta_generic_to_shared(&Bs[0][0]);
    sB[1] = (uint32_t)__cvta_generic_to_shared(&Bs[1][0]);

    // precompute load coordinates
    const int a_r0 = (tid * 2) >> 2;          // 2 float4 per thread for A
    const int a_c0 = ((tid * 2) & 3) * 4;
    const int a_r1 = (tid * 2 + 1) >> 2;
    const int a_c1 = ((tid * 2 + 1) & 3) * 4;
    const int b_r0 = (tid * 2) >> 5;
    const int b_c0 = ((tid * 2) & 31) * 4;
    const int b_r1 = (tid * 2 + 1) >> 5;
    const int b_c1 = ((tid * 2 + 1) & 31) * 4;

#define LOAD_STAGE(stage, k0)                                                        \
    do {                                                                             \
        cp_async16(sA[stage] + (uint32_t)(a_r0 * S_A + a_c0) * 4,                    \
                   A + (size_t)(row0 + a_r0) * 256 + (k0) + a_c0, row0 + a_r0 < M);  \
        cp_async16(sA[stage] + (uint32_t)(a_r1 * S_A + a_c1) * 4,                    \
                   A + (size_t)(row0 + a_r1) * 256 + (k0) + a_c1, row0 + a_r1 < M);  \
        cp_async16(sB[stage] + (uint32_t)(b_r0 * S_B + b_c0) * 4,                    \
                   B + (size_t)((k0) + b_r0) * 256 + col0 + b_c0, true);             \
        cp_async16(sB[stage] + (uint32_t)(b_r1 * S_B + b_c1) * 4,                    \
                   B + (size_t)((k0) + b_r1) * 256 + col0 + b_c1, true);             \
        asm volatile("cp.async.commit_group;\n");                                    \
    } while (0)

    LOAD_STAGE(0, 0);
    asm volatile("cp.async.wait_group 0;\n");
    __syncthreads();

    for (int k0 = 0; k0 < 256; k0 += BK) {
        const int cur = (k0 / BK) & 1;
        const int nxt = cur ^ 1;
        const bool more = (k0 + BK) < 256;
        if (more) LOAD_STAGE(nxt, k0 + BK);

        const float* as = &As[cur][0];
        const float* bs = &Bs[cur][0];

#pragma unroll
        for (int ks = 0; ks < 2; ks++) {
            const int kl = ks * 8;
            uint32_t af[2][4];
            uint32_t bf[8][2];
#pragma unroll
            for (int mt = 0; mt < 2; mt++) {
                int mb = warp_m + mt * 16;
                af[mt][0] = f2tf32(as[(mb + g) * S_A + kl + t]);
                af[mt][1] = f2tf32(as[(mb + g + 8) * S_A + kl + t]);
                af[mt][2] = f2tf32(as[(mb + g) * S_A + kl + t + 4]);
                af[mt][3] = f2tf32(as[(mb + g + 8) * S_A + kl + t + 4]);
            }
#pragma unroll
            for (int nt = 0; nt < 8; nt++) {
                int nb = warp_n + nt * 8 + g;
                bf[nt][0] = f2tf32(bs[(kl + t) * S_B + nb]);
                bf[nt][1] = f2tf32(bs[(kl + t + 4) * S_B + nb]);
            }
#pragma unroll
            for (int mt = 0; mt < 2; mt++)
#pragma unroll
                for (int nt = 0; nt < 8; nt++) {
                    asm volatile(
                        "mma.sync.aligned.m16n8k8.row.col.f32.tf32.tf32.f32 "
                        "{%0,%1,%2,%3}, {%4,%5,%6,%7}, {%8,%9}, {%0,%1,%2,%3};"
                        : "+f"(c[mt][nt][0]), "+f"(c[mt][nt][1]),
                          "+f"(c[mt][nt][2]), "+f"(c[mt][nt][3])
                        : "r"(af[mt][0]), "r"(af[mt][1]), "r"(af[mt][2]), "r"(af[mt][3]),
                          "r"(bf[nt][0]), "r"(bf[nt][1]));
                }
        }

        if (more) asm volatile("cp.async.wait_group 0;\n");
        __syncthreads();
    }

    // epilogue: c0,c1 -> (row g, cols 2t,2t+1); c2,c3 -> (row g+8)
#pragma unroll
    for (int mt = 0; mt < 2; mt++) {
        int r1 = row0 + warp_m + mt * 16 + g;
        int r2 = r1 + 8;
#pragma unroll
        for (int nt = 0; nt < 8; nt++) {
            int cc = col0 + warp_n + nt * 8 + t * 2;
            if (r1 < M)
                *reinterpret_cast<float2*>(&C[(size_t)r1 * 256 + cc]) =
                    make_float2(c[mt][nt][0], c[mt][nt][1]);
            if (r2 < M)
                *reinterpret_cast<float2*>(&C[(size_t)r2 * 256 + cc]) =
                    make_float2(c[mt][nt][2], c[mt][nt][3]);
        }
    }
#undef LOAD_STAGE
}

// ---------------------------------------------------------------------------
// SpMM by destination (CSR): one warp per node, register accumulation,
// fused ReLU + single store.
// ---------------------------------------------------------------------------
__global__ __launch_bounds__(256) void spmm_csr_kernel(
    const int* __restrict__ off, const int* __restrict__ cnt,
    const int* __restrict__ ssrc, const float* __restrict__ sval,
    const float* __restrict__ x, float* __restrict__ out, int N)
{
    int warp = (blockIdx.x * blockDim.x + threadIdx.x) >> 5;
    int lane = threadIdx.x & 31;
    if (warp >= N) return;

    int beg = off[warp];
    int end = beg + cnt[warp];

    float4 acc0 = make_float4(0.f, 0.f, 0.f, 0.f);
    float4 acc1 = make_float4(0.f, 0.f, 0.f, 0.f);

    int e = beg;
    for (; e + 2 <= end; e += 2) {
        int s0 = ssrc[e],   s1 = ssrc[e + 1];
        float v0 = sval[e], v1 = sval[e + 1];
        const float4* p0 = reinterpret_cast<const float4*>(x + (size_t)s0 * D) + lane * 2;
        const float4* p1 = reinterpret_cast<const float4*>(x + (size_t)s1 * D) + lane * 2;
        float4 a0 = __ldg(p0), b0 = __ldg(p0 + 1);
        float4 a1 = __ldg(p1), b1 = __ldg(p1 + 1);
        acc0.x = fmaf(v0, a0.x, acc0.x); acc0.y = fmaf(v0, a0.y, acc0.y);
        acc0.z = fmaf(v0, a0.z, acc0.z); acc0.w = fmaf(v0, a0.w, acc0.w);
        acc1.x = fmaf(v0, b0.x, acc1.x); acc1.y = fmaf(v0, b0.y, acc1.y);
        acc1.z = fmaf(v0, b0.z, acc1.z); acc1.w = fmaf(v0, b0.w, acc1.w);
        acc0.x = fmaf(v1, a1.x, acc0.x); acc0.y = fmaf(v1, a1.y, acc0.y);
        acc0.z = fmaf(v1, a1.z, acc0.z); acc0.w = fmaf(v1, a1.w, acc0.w);
        acc1.x = fmaf(v1, b1.x, acc1.x); acc1.y = fmaf(v1, b1.y, acc1.y);
        acc1.z = fmaf(v1, b1.z, acc1.z); acc1.w = fmaf(v1, b1.w, acc1.w);
    }
    if (e < end) {
        int s0 = ssrc[e];
        float v0 = sval[e];
        const float4* p0 = reinterpret_cast<const float4*>(x + (size_t)s0 * D) + lane * 2;
        float4 a0 = __ldg(p0), b0 = __ldg(p0 + 1);
        acc0.x = fmaf(v0, a0.x, acc0.x); acc0.y = fmaf(v0, a0.y, acc0.y);
        acc0.z = fmaf(v0, a0.z, acc0.z); acc0.w = fmaf(v0, a0.w, acc0.w);
        acc1.x = fmaf(v0, b0.x, acc1.x); acc1.y = fmaf(v0, b0.y, acc1.y);
        acc1.z = fmaf(v0, b0.z, acc1.z); acc1.w = fmaf(v0, b0.w, acc1.w);
    }

    acc0.x = fmaxf(acc0.x, 0.f); acc0.y = fmaxf(acc0.y, 0.f);
    acc0.z = fmaxf(acc0.z, 0.f); acc0.w = fmaxf(acc0.w, 0.f);
    acc1.x = fmaxf(acc1.x, 0.f); acc1.y = fmaxf(acc1.y, 0.f);
    acc1.z = fmaxf(acc1.z, 0.f); acc1.w = fmaxf(acc1.w, 0.f);

    float4* o = reinterpret_cast<float4*>(out + (size_t)warp * D) + lane * 2;
    o[0] = acc0;
    o[1] = acc1;
}

// ---------------------------------------------------------------------------
// Launcher
// ---------------------------------------------------------------------------
extern "C" void kernel_launch(void* const* d_in, const int* in_sizes, int n_in,
                              void* d_out, int out_size)
{
    const float* inputs = (const float*)d_in[0];
    const float* W      = (const float*)d_in[1];
    const int*   esrc   = (const int*)  d_in[2];
    const int*   edst   = (const int*)  d_in[3];
    const float* evals  = (const float*)d_in[4];
    float*       out    = (float*)d_out;

    const int M = in_sizes[0] / D;     // 100000
    const int E = in_sizes[2];         // 3200000

    float *x, *sval;
    int *cnt, *off, *cur, *bsum, *ssrc;
    cudaGetSymbolAddress((void**)&x,    g_x);
    cudaGetSymbolAddress((void**)&cnt,  g_cnt);
    cudaGetSymbolAddress((void**)&off,  g_off);
    cudaGetSymbolAddress((void**)&cur,  g_cur);
    cudaGetSymbolAddress((void**)&bsum, g_bsum);
    cudaGetSymbolAddress((void**)&ssrc, g_ssrc);
    cudaGetSymbolAddress((void**)&sval, g_sval);

    const int nblocks_scan = (M + SCAN_BLK - 1) / SCAN_BLK;

    // ---- CSR build ----
    zero_cnt_kernel<<<(M + 255) / 256, 256>>>(cnt, M);
    hist_kernel<<<(E + 255) / 256, 256>>>(edst, cnt, E);
    scan1_kernel<<<nblocks_scan, SCAN_BLK>>>(cnt, off, bsum, M);
    scan2_kernel<<<1, SCAN_BLK>>>(bsum, nblocks_scan);
    scan3_kernel<<<(M + 255) / 256, 256>>>(off, bsum, cur, M);
    scatter_kernel<<<(E + 255) / 256, 256>>>(esrc, edst, evals, cur, ssrc, sval, E);

    // ---- x = inputs @ W (tf32 tensor cores) ----
    {
        dim3 grid((M + BM - 1) / BM, 256 / BN);
        gemm_tf32_kernel<<<grid, 256>>>(inputs, W, x, M);
    }

    // ---- SpMM-CSR + fused ReLU ----
    {
        long long threads = (long long)M * 32;
        int blocks = (int)((threads + 255) / 256);
        spmm_csr_kernel<<<blocks, 256>>>(off, cnt, ssrc, sval, x, out, M);
    }
}

// round 6
// speedup vs baseline: 4.7532x; 1.4077x over previous
#include <cuda_runtime.h>
#include <cuda_fp16.h>
#include <cstdint>

#define D 256
#define MAX_NODES 100000
#define MAX_EDGES 3200000
#define SCAN_BLK 1024

// ---- device scratch (static: allocation rules) ----
static __device__ __half g_xh[(size_t)MAX_NODES * D];   // inputs @ W, fp16
static __device__ int    g_off[MAX_NODES + 1];          // CSR offsets (exclusive, +total)
static __device__ int    g_cur[MAX_NODES];              // scatter cursor / histogram
static __device__ int    g_bsum[(MAX_NODES + SCAN_BLK - 1) / SCAN_BLK + 1];
static __device__ int    g_ssrc[MAX_EDGES];             // src sorted by dst
static __device__ float  g_sval[MAX_EDGES];             // val sorted by dst

// ---------------------------------------------------------------------------
// CSR build
// ---------------------------------------------------------------------------
__global__ __launch_bounds__(256) void hist_kernel(
    const int* __restrict__ edst, int* __restrict__ cnt, int E)
{
    int i = blockIdx.x * blockDim.x + threadIdx.x;
    if (i < E) atomicAdd(&cnt[edst[i]], 1);
}

__global__ __launch_bounds__(SCAN_BLK) void scan1_kernel(
    const int* __restrict__ cnt, int* __restrict__ off, int* __restrict__ bsum, int n)
{
    __shared__ int s[SCAN_BLK];
    int tid = threadIdx.x;
    int i = blockIdx.x * SCAN_BLK + tid;
    int v = (i < n) ? cnt[i] : 0;
    s[tid] = v;
    __syncthreads();
#pragma unroll
    for (int d = 1; d < SCAN_BLK; d <<= 1) {
        int t = (tid >= d) ? s[tid - d] : 0;
        __syncthreads();
        s[tid] += t;
        __syncthreads();
    }
    if (i < n) off[i] = s[tid] - v;
    if (tid == SCAN_BLK - 1) bsum[blockIdx.x] = s[tid];
}

__global__ __launch_bounds__(SCAN_BLK) void scan2_kernel(int* __restrict__ bsum, int nb)
{
    __shared__ int s[SCAN_BLK];
    int tid = threadIdx.x;
    int v = (tid < nb) ? bsum[tid] : 0;
    s[tid] = v;
    __syncthreads();
#pragma unroll
    for (int d = 1; d < SCAN_BLK; d <<= 1) {
        int t = (tid >= d) ? s[tid - d] : 0;
        __syncthreads();
        s[tid] += t;
        __syncthreads();
    }
    if (tid < nb) bsum[tid] = s[tid] - v;
}

__global__ __launch_bounds__(256) void scan3_kernel(
    int* __restrict__ off, const int* __restrict__ bsum, int* __restrict__ cur,
    int n, int E)
{
    int i = blockIdx.x * blockDim.x + threadIdx.x;
    if (i < n) {
        int o = off[i] + bsum[i / SCAN_BLK];
        off[i] = o;
        cur[i] = o;
    }
    if (i == n) off[n] = E;
}

__global__ __launch_bounds__(256) void scatter_kernel(
    const int* __restrict__ esrc, const int* __restrict__ edst,
    const float* __restrict__ evals, int* __restrict__ cur,
    int* __restrict__ ssrc, float* __restrict__ sval, int E)
{
    int i = blockIdx.x * blockDim.x + threadIdx.x;
    if (i < E) {
        int d = edst[i];
        int pos = atomicAdd(&cur[d], 1);
        ssrc[pos] = esrc[i];
        sval[pos] = evals[i];
    }
}

// ---------------------------------------------------------------------------
// tf32 tensor-core GEMM: Xh[M,256] = A[M,256] @ B[256,256], fp16 output
// CTA 128x128, 8 warps, warp tile 32x64, BK=16, cp.async double buffer
// ---------------------------------------------------------------------------
#define BM 128
#define BN 128
#define BK 16
#define S_A 20
#define S_B 136

__device__ __forceinline__ void cp_async16(uint32_t dst, const void* src, bool valid)
{
    int sz = valid ? 16 : 0;
    asm volatile("cp.async.ca.shared.global [%0], [%1], 16, %2;\n"
                 :: "r"(dst), "l"(src), "r"(sz));
}

__device__ __forceinline__ uint32_t f2tf32(float f)
{
    uint32_t u;
    asm("cvt.rna.tf32.f32 %0, %1;" : "=r"(u) : "f"(f));
    return u;
}

__global__ __launch_bounds__(256, 2) void gemm_tf32_kernel(
    const float* __restrict__ A, const float* __restrict__ B,
    __half* __restrict__ C, int M)
{
    __shared__ float As[2][BM * S_A];
    __shared__ float Bs[2][BK * S_B];

    const int tid = threadIdx.x;
    const int lane = tid & 31;
    const int wid = tid >> 5;
    const int g = lane >> 2;
    const int t = lane & 3;
    const int warp_m = (wid >> 1) * 32;
    const int warp_n = (wid & 1) * 64;
    const int row0 = blockIdx.x * BM;
    const int col0 = blockIdx.y * BN;

    float c[2][8][4];
#pragma unroll
    for (int i = 0; i < 2; i++)
#pragma unroll
        for (int j = 0; j < 8; j++)
#pragma unroll
            for (int k = 0; k < 4; k++) c[i][j][k] = 0.f;

    uint32_t sA[2], sB[2];
    sA[0] = (uint32_t)__cvta_generic_to_shared(&As[0][0]);
    sA[1] = (uint32_t)__cvta_generic_to_shared(&As[1][0]);
    sB[0] = (uint32_t)__cvta_generic_to_shared(&Bs[0][0]);
    sB[1] = (uint32_t)__cvta_generic_to_shared(&Bs[1][0]);

    const int a_r0 = (tid * 2) >> 2;
    const int a_c0 = ((tid * 2) & 3) * 4;
    const int a_r1 = (tid * 2 + 1) >> 2;
    const int a_c1 = ((tid * 2 + 1) & 3) * 4;
    const int b_r0 = (tid * 2) >> 5;
    const int b_c0 = ((tid * 2) & 31) * 4;
    const int b_r1 = (tid * 2 + 1) >> 5;
    const int b_c1 = ((tid * 2 + 1) & 31) * 4;

#define LOAD_STAGE(stage, k0)                                                        \
    do {                                                                             \
        cp_async16(sA[stage] + (uint32_t)(a_r0 * S_A + a_c0) * 4,                    \
                   A + (size_t)(row0 + a_r0) * 256 + (k0) + a_c0, row0 + a_r0 < M);  \
        cp_async16(sA[stage] + (uint32_t)(a_r1 * S_A + a_c1) * 4,                    \
                   A + (size_t)(row0 + a_r1) * 256 + (k0) + a_c1, row0 + a_r1 < M);  \
        cp_async16(sB[stage] + (uint32_t)(b_r0 * S_B + b_c0) * 4,                    \
                   B + (size_t)((k0) + b_r0) * 256 + col0 + b_c0, true);             \
        cp_async16(sB[stage] + (uint32_t)(b_r1 * S_B + b_c1) * 4,                    \
                   B + (size_t)((k0) + b_r1) * 256 + col0 + b_c1, true);             \
        asm volatile("cp.async.commit_group;\n");                                    \
    } while (0)

    LOAD_STAGE(0, 0);
    asm volatile("cp.async.wait_group 0;\n");
    __syncthreads();

    for (int k0 = 0; k0 < 256; k0 += BK) {
        const int cur = (k0 / BK) & 1;
        const int nxt = cur ^ 1;
        const bool more = (k0 + BK) < 256;
        if (more) LOAD_STAGE(nxt, k0 + BK);

        const float* as = &As[cur][0];
        const float* bs = &Bs[cur][0];

#pragma unroll
        for (int ks = 0; ks < 2; ks++) {
            const int kl = ks * 8;
            uint32_t af[2][4];
            uint32_t bf[8][2];
#pragma unroll
            for (int mt = 0; mt < 2; mt++) {
                int mb = warp_m + mt * 16;
                af[mt][0] = f2tf32(as[(mb + g) * S_A + kl + t]);
                af[mt][1] = f2tf32(as[(mb + g + 8) * S_A + kl + t]);
                af[mt][2] = f2tf32(as[(mb + g) * S_A + kl + t + 4]);
                af[mt][3] = f2tf32(as[(mb + g + 8) * S_A + kl + t + 4]);
            }
#pragma unroll
            for (int nt = 0; nt < 8; nt++) {
                int nb = warp_n + nt * 8 + g;
                bf[nt][0] = f2tf32(bs[(kl + t) * S_B + nb]);
                bf[nt][1] = f2tf32(bs[(kl + t + 4) * S_B + nb]);
            }
#pragma unroll
            for (int mt = 0; mt < 2; mt++)
#pragma unroll
                for (int nt = 0; nt < 8; nt++) {
                    asm volatile(
                        "mma.sync.aligned.m16n8k8.row.col.f32.tf32.tf32.f32 "
                        "{%0,%1,%2,%3}, {%4,%5,%6,%7}, {%8,%9}, {%0,%1,%2,%3};"
                        : "+f"(c[mt][nt][0]), "+f"(c[mt][nt][1]),
                          "+f"(c[mt][nt][2]), "+f"(c[mt][nt][3])
                        : "r"(af[mt][0]), "r"(af[mt][1]), "r"(af[mt][2]), "r"(af[mt][3]),
                          "r"(bf[nt][0]), "r"(bf[nt][1]));
                }
        }

        if (more) asm volatile("cp.async.wait_group 0;\n");
        __syncthreads();
    }

    // epilogue: fp32 -> fp16 (half2 stores)
#pragma unroll
    for (int mt = 0; mt < 2; mt++) {
        int r1 = row0 + warp_m + mt * 16 + g;
        int r2 = r1 + 8;
#pragma unroll
        for (int nt = 0; nt < 8; nt++) {
            int cc = col0 + warp_n + nt * 8 + t * 2;
            if (r1 < M)
                *reinterpret_cast<__half2*>(&C[(size_t)r1 * 256 + cc]) =
                    __floats2half2_rn(c[mt][nt][0], c[mt][nt][1]);
            if (r2 < M)
                *reinterpret_cast<__half2*>(&C[(size_t)r2 * 256 + cc]) =
                    __floats2half2_rn(c[mt][nt][2], c[mt][nt][3]);
        }
    }
#undef LOAD_STAGE
}

// ---------------------------------------------------------------------------
// SpMM-CSR: one warp per node; fp16 gather (one LDG.128 per edge per lane),
// fp32 accumulate, fused ReLU, single fp32 store.
// ---------------------------------------------------------------------------
__device__ __forceinline__ float2 h2f2(uint32_t packed)
{
    __half2 h = *reinterpret_cast<__half2*>(&packed);
    return __half22float2(h);
}

__device__ __forceinline__ void acc_row(
    float4& a0, float4& a1, uint4 r, float v)
{
    float2 f;
    f = h2f2(r.x);
    a0.x = fmaf(v, f.x, a0.x); a0.y = fmaf(v, f.y, a0.y);
    f = h2f2(r.y);
    a0.z = fmaf(v, f.x, a0.z); a0.w = fmaf(v, f.y, a0.w);
    f = h2f2(r.z);
    a1.x = fmaf(v, f.x, a1.x); a1.y = fmaf(v, f.y, a1.y);
    f = h2f2(r.w);
    a1.z = fmaf(v, f.x, a1.z); a1.w = fmaf(v, f.y, a1.w);
}

__global__ __launch_bounds__(256) void spmm_csr_kernel(
    const int* __restrict__ off,
    const int* __restrict__ ssrc, const float* __restrict__ sval,
    const __half* __restrict__ x, float* __restrict__ out, int N)
{
    int warp = (blockIdx.x * blockDim.x + threadIdx.x) >> 5;
    int lane = threadIdx.x & 31;
    if (warp >= N) return;

    int beg = off[warp];
    int end = off[warp + 1];

    float4 acc0 = make_float4(0.f, 0.f, 0.f, 0.f);
    float4 acc1 = make_float4(0.f, 0.f, 0.f, 0.f);

    int e = beg;
    // 4-edge unroll: 4 outstanding LDG.128 per lane
    for (; e + 4 <= end; e += 4) {
        int s0 = ssrc[e], s1 = ssrc[e + 1], s2 = ssrc[e + 2], s3 = ssrc[e + 3];
        float v0 = sval[e], v1 = sval[e + 1], v2 = sval[e + 2], v3 = sval[e + 3];
        uint4 r0 = __ldg(reinterpret_cast<const uint4*>(x + (size_t)s0 * D) + lane);
        uint4 r1 = __ldg(reinterpret_cast<const uint4*>(x + (size_t)s1 * D) + lane);
        uint4 r2 = __ldg(reinterpret_cast<const uint4*>(x + (size_t)s2 * D) + lane);
        uint4 r3 = __ldg(reinterpret_cast<const uint4*>(x + (size_t)s3 * D) + lane);
        acc_row(acc0, acc1, r0, v0);
        acc_row(acc0, acc1, r1, v1);
        acc_row(acc0, acc1, r2, v2);
        acc_row(acc0, acc1, r3, v3);
    }
    for (; e < end; e++) {
        int s0 = ssrc[e];
        float v0 = sval[e];
        uint4 r0 = __ldg(reinterpret_cast<const uint4*>(x + (size_t)s0 * D) + lane);
        acc_row(acc0, acc1, r0, v0);
    }

    acc0.x = fmaxf(acc0.x, 0.f); acc0.y = fmaxf(acc0.y, 0.f);
    acc0.z = fmaxf(acc0.z, 0.f); acc0.w = fmaxf(acc0.w, 0.f);
    acc1.x = fmaxf(acc1.x, 0.f); acc1.y = fmaxf(acc1.y, 0.f);
    acc1.z = fmaxf(acc1.z, 0.f); acc1.w = fmaxf(acc1.w, 0.f);

    float4* o = reinterpret_cast<float4*>(out + (size_t)warp * D) + lane * 2;
    o[0] = acc0;
    o[1] = acc1;
}

// ---------------------------------------------------------------------------
// Launcher
// ---------------------------------------------------------------------------
extern "C" void kernel_launch(void* const* d_in, const int* in_sizes, int n_in,
                              void* d_out, int out_size)
{
    const float* inputs = (const float*)d_in[0];
    const float* W      = (const float*)d_in[1];
    const int*   esrc   = (const int*)  d_in[2];
    const int*   edst   = (const int*)  d_in[3];
    const float* evals  = (const float*)d_in[4];
    float*       out    = (float*)d_out;

    const int M = in_sizes[0] / D;     // 100000
    const int E = in_sizes[2];         // 3200000

    __half* xh;
    float* sval;
    int *off, *cur, *bsum, *ssrc;
    cudaGetSymbolAddress((void**)&xh,   g_xh);
    cudaGetSymbolAddress((void**)&off,  g_off);
    cudaGetSymbolAddress((void**)&cur,  g_cur);
    cudaGetSymbolAddress((void**)&bsum, g_bsum);
    cudaGetSymbolAddress((void**)&ssrc, g_ssrc);
    cudaGetSymbolAddress((void**)&sval, g_sval);

    const int nblocks_scan = (M + SCAN_BLK - 1) / SCAN_BLK;

    // ---- CSR build ----
    cudaMemsetAsync(cur, 0, M * sizeof(int));
    hist_kernel<<<(E + 255) / 256, 256>>>(edst, cur, E);
    scan1_kernel<<<nblocks_scan, SCAN_BLK>>>(cur, off, bsum, M);
    scan2_kernel<<<1, SCAN_BLK>>>(bsum, nblocks_scan);
    scan3_kernel<<<(M + 256) / 256, 256>>>(off, bsum, cur, M, E);
    scatter_kernel<<<(E + 255) / 256, 256>>>(esrc, edst, evals, cur, ssrc, sval, E);

    // ---- x = inputs @ W (tf32 -> fp16) ----
    {
        dim3 grid((M + BM - 1) / BM, 256 / BN);
        gemm_tf32_kernel<<<grid, 256>>>(inputs, W, xh, M);
    }

    // ---- SpMM-CSR + fused ReLU ----
    {
        long long threads = (long long)M * 32;
        int blocks = (int)((threads + 255) / 256);
        spmm_csr_kernel<<<blocks, 256>>>(off, ssrc, sval, xh, out, M);
    }
}

// round 7
// speedup vs baseline: 4.9324x; 1.0377x over previous
#include <cuda_runtime.h>
#include <cuda_fp16.h>
#include <cstdint>

#define D 256
#define MAX_NODES 100000
#define MAX_EDGES 3200000
#define SCAN_BLK 1024

// ---- device scratch (static: allocation rules) ----
static __device__ __half g_xh[(size_t)MAX_NODES * D];   // inputs @ W, fp16
static __device__ int    g_off[MAX_NODES + 1];          // CSR offsets
static __device__ int    g_cur[MAX_NODES];              // histogram / scatter cursor
static __device__ int    g_bsum[(MAX_NODES + SCAN_BLK - 1) / SCAN_BLK + 1];
static __device__ int2   g_edge[MAX_EDGES];             // packed (src, val) sorted by dst

// ---------------------------------------------------------------------------
// CSR build
// ---------------------------------------------------------------------------
__global__ __launch_bounds__(256) void hist_kernel(
    const int* __restrict__ edst, int* __restrict__ cnt, int E)
{
    int i = blockIdx.x * blockDim.x + threadIdx.x;
    if (i < E) atomicAdd(&cnt[edst[i]], 1);
}

__global__ __launch_bounds__(SCAN_BLK) void scan1_kernel(
    const int* __restrict__ cnt, int* __restrict__ off, int* __restrict__ bsum, int n)
{
    __shared__ int s[SCAN_BLK];
    int tid = threadIdx.x;
    int i = blockIdx.x * SCAN_BLK + tid;
    int v = (i < n) ? cnt[i] : 0;
    s[tid] = v;
    __syncthreads();
#pragma unroll
    for (int d = 1; d < SCAN_BLK; d <<= 1) {
        int t = (tid >= d) ? s[tid - d] : 0;
        __syncthreads();
        s[tid] += t;
        __syncthreads();
    }
    if (i < n) off[i] = s[tid] - v;
    if (tid == SCAN_BLK - 1) bsum[blockIdx.x] = s[tid];
}

__global__ __launch_bounds__(SCAN_BLK) void scan2_kernel(int* __restrict__ bsum, int nb)
{
    __shared__ int s[SCAN_BLK];
    int tid = threadIdx.x;
    int v = (tid < nb) ? bsum[tid] : 0;
    s[tid] = v;
    __syncthreads();
#pragma unroll
    for (int d = 1; d < SCAN_BLK; d <<= 1) {
        int t = (tid >= d) ? s[tid - d] : 0;
        __syncthreads();
        s[tid] += t;
        __syncthreads();
    }
    if (tid < nb) bsum[tid] = s[tid] - v;
}

__global__ __launch_bounds__(256) void scan3_kernel(
    int* __restrict__ off, const int* __restrict__ bsum, int* __restrict__ cur,
    int n, int E)
{
    int i = blockIdx.x * blockDim.x + threadIdx.x;
    if (i < n) {
        int o = off[i] + bsum[i / SCAN_BLK];
        off[i] = o;
        cur[i] = o;
    }
    if (i == n) off[n] = E;
}

__global__ __launch_bounds__(256) void scatter_kernel(
    const int* __restrict__ esrc, const int* __restrict__ edst,
    const float* __restrict__ evals, int* __restrict__ cur,
    int2* __restrict__ edge, int E)
{
    int i = blockIdx.x * blockDim.x + threadIdx.x;
    if (i < E) {
        int d = edst[i];
        int pos = atomicAdd(&cur[d], 1);
        edge[pos] = make_int2(esrc[i], __float_as_int(evals[i]));
    }
}

// ---------------------------------------------------------------------------
// tf32 tensor-core GEMM: Xh[M,256] = A[M,256] @ B[256,256], fp16 output
// ---------------------------------------------------------------------------
#define BM 128
#define BN 128
#define BK 16
#define S_A 20
#define S_B 136

__device__ __forceinline__ void cp_async16(uint32_t dst, const void* src, bool valid)
{
    int sz = valid ? 16 : 0;
    asm volatile("cp.async.ca.shared.global [%0], [%1], 16, %2;\n"
                 :: "r"(dst), "l"(src), "r"(sz));
}

__device__ __forceinline__ uint32_t f2tf32(float f)
{
    uint32_t u;
    asm("cvt.rna.tf32.f32 %0, %1;" : "=r"(u) : "f"(f));
    return u;
}

__global__ __launch_bounds__(256, 2) void gemm_tf32_kernel(
    const float* __restrict__ A, const float* __restrict__ B,
    __half* __restrict__ C, int M)
{
    __shared__ float As[2][BM * S_A];
    __shared__ float Bs[2][BK * S_B];

    const int tid = threadIdx.x;
    const int lane = tid & 31;
    const int wid = tid >> 5;
    const int g = lane >> 2;
    const int t = lane & 3;
    const int warp_m = (wid >> 1) * 32;
    const int warp_n = (wid & 1) * 64;
    const int row0 = blockIdx.x * BM;
    const int col0 = blockIdx.y * BN;

    float c[2][8][4];
#pragma unroll
    for (int i = 0; i < 2; i++)
#pragma unroll
        for (int j = 0; j < 8; j++)
#pragma unroll
            for (int k = 0; k < 4; k++) c[i][j][k] = 0.f;

    uint32_t sA[2], sB[2];
    sA[0] = (uint32_t)__cvta_generic_to_shared(&As[0][0]);
    sA[1] = (uint32_t)__cvta_generic_to_shared(&As[1][0]);
    sB[0] = (uint32_t)__cvta_generic_to_shared(&Bs[0][0]);
    sB[1] = (uint32_t)__cvta_generic_to_shared(&Bs[1][0]);

    const int a_r0 = (tid * 2) >> 2;
    const int a_c0 = ((tid * 2) & 3) * 4;
    const int a_r1 = (tid * 2 + 1) >> 2;
    const int a_c1 = ((tid * 2 + 1) & 3) * 4;
    const int b_r0 = (tid * 2) >> 5;
    const int b_c0 = ((tid * 2) & 31) * 4;
    const int b_r1 = (tid * 2 + 1) >> 5;
    const int b_c1 = ((tid * 2 + 1) & 31) * 4;

#define LOAD_STAGE(stage, k0)                                                        \
    do {                                                                             \
        cp_async16(sA[stage] + (uint32_t)(a_r0 * S_A + a_c0) * 4,                    \
                   A + (size_t)(row0 + a_r0) * 256 + (k0) + a_c0, row0 + a_r0 < M);  \
        cp_async16(sA[stage] + (uint32_t)(a_r1 * S_A + a_c1) * 4,                    \
                   A + (size_t)(row0 + a_r1) * 256 + (k0) + a_c1, row0 + a_r1 < M);  \
        cp_async16(sB[stage] + (uint32_t)(b_r0 * S_B + b_c0) * 4,                    \
                   B + (size_t)((k0) + b_r0) * 256 + col0 + b_c0, true);             \
        cp_async16(sB[stage] + (uint32_t)(b_r1 * S_B + b_c1) * 4,                    \
                   B + (size_t)((k0) + b_r1) * 256 + col0 + b_c1, true);             \
        asm volatile("cp.async.commit_group;\n");                                    \
    } while (0)

    LOAD_STAGE(0, 0);
    asm volatile("cp.async.wait_group 0;\n");
    __syncthreads();

    for (int k0 = 0; k0 < 256; k0 += BK) {
        const int cur = (k0 / BK) & 1;
        const int nxt = cur ^ 1;
        const bool more = (k0 + BK) < 256;
        if (more) LOAD_STAGE(nxt, k0 + BK);

        const float* as = &As[cur][0];
        const float* bs = &Bs[cur][0];

#pragma unroll
        for (int ks = 0; ks < 2; ks++) {
            const int kl = ks * 8;
            uint32_t af[2][4];
            uint32_t bf[8][2];
#pragma unroll
            for (int mt = 0; mt < 2; mt++) {
                int mb = warp_m + mt * 16;
                af[mt][0] = f2tf32(as[(mb + g) * S_A + kl + t]);
                af[mt][1] = f2tf32(as[(mb + g + 8) * S_A + kl + t]);
                af[mt][2] = f2tf32(as[(mb + g) * S_A + kl + t + 4]);
                af[mt][3] = f2tf32(as[(mb + g + 8) * S_A + kl + t + 4]);
            }
#pragma unroll
            for (int nt = 0; nt < 8; nt++) {
                int nb = warp_n + nt * 8 + g;
                bf[nt][0] = f2tf32(bs[(kl + t) * S_B + nb]);
                bf[nt][1] = f2tf32(bs[(kl + t + 4) * S_B + nb]);
            }
#pragma unroll
            for (int mt = 0; mt < 2; mt++)
#pragma unroll
                for (int nt = 0; nt < 8; nt++) {
                    asm volatile(
                        "mma.sync.aligned.m16n8k8.row.col.f32.tf32.tf32.f32 "
                        "{%0,%1,%2,%3}, {%4,%5,%6,%7}, {%8,%9}, {%0,%1,%2,%3};"
                        : "+f"(c[mt][nt][0]), "+f"(c[mt][nt][1]),
                          "+f"(c[mt][nt][2]), "+f"(c[mt][nt][3])
                        : "r"(af[mt][0]), "r"(af[mt][1]), "r"(af[mt][2]), "r"(af[mt][3]),
                          "r"(bf[nt][0]), "r"(bf[nt][1]));
                }
        }

        if (more) asm volatile("cp.async.wait_group 0;\n");
        __syncthreads();
    }

#pragma unroll
    for (int mt = 0; mt < 2; mt++) {
        int r1 = row0 + warp_m + mt * 16 + g;
        int r2 = r1 + 8;
#pragma unroll
        for (int nt = 0; nt < 8; nt++) {
            int cc = col0 + warp_n + nt * 8 + t * 2;
            if (r1 < M)
                *reinterpret_cast<__half2*>(&C[(size_t)r1 * 256 + cc]) =
                    __floats2half2_rn(c[mt][nt][0], c[mt][nt][1]);
            if (r2 < M)
                *reinterpret_cast<__half2*>(&C[(size_t)r2 * 256 + cc]) =
                    __floats2half2_rn(c[mt][nt][2], c[mt][nt][3]);
        }
    }
#undef LOAD_STAGE
}

// ---------------------------------------------------------------------------
// SpMM-CSR: one warp per node; packed int2 edges; fp16 gather, fp32 accumulate,
// fused ReLU, single store.
// ---------------------------------------------------------------------------
__device__ __forceinline__ float2 h2f2(uint32_t packed)
{
    __half2 h = *reinterpret_cast<__half2*>(&packed);
    return __half22float2(h);
}

__device__ __forceinline__ void acc_row(
    float4& a0, float4& a1, uint4 r, float v)
{
    float2 f;
    f = h2f2(r.x);
    a0.x = fmaf(v, f.x, a0.x); a0.y = fmaf(v, f.y, a0.y);
    f = h2f2(r.y);
    a0.z = fmaf(v, f.x, a0.z); a0.w = fmaf(v, f.y, a0.w);
    f = h2f2(r.z);
    a1.x = fmaf(v, f.x, a1.x); a1.y = fmaf(v, f.y, a1.y);
    f = h2f2(r.w);
    a1.z = fmaf(v, f.x, a1.z); a1.w = fmaf(v, f.y, a1.w);
}

__global__ __launch_bounds__(256) void spmm_csr_kernel(
    const int* __restrict__ off, const int2* __restrict__ edge,
    const __half* __restrict__ x, float* __restrict__ out, int N)
{
    int warp = (blockIdx.x * blockDim.x + threadIdx.x) >> 5;
    int lane = threadIdx.x & 31;
    if (warp >= N) return;

    int beg = off[warp];
    int end = off[warp + 1];

    float4 acc0 = make_float4(0.f, 0.f, 0.f, 0.f);
    float4 acc1 = make_float4(0.f, 0.f, 0.f, 0.f);

    int e = beg;
    for (; e + 4 <= end; e += 4) {
        int2 e0 = edge[e],     e1 = edge[e + 1];
        int2 e2 = edge[e + 2], e3 = edge[e + 3];
        uint4 r0 = __ldg(reinterpret_cast<const uint4*>(x + (size_t)e0.x * D) + lane);
        uint4 r1 = __ldg(reinterpret_cast<const uint4*>(x + (size_t)e1.x * D) + lane);
        uint4 r2 = __ldg(reinterpret_cast<const uint4*>(x + (size_t)e2.x * D) + lane);
        uint4 r3 = __ldg(reinterpret_cast<const uint4*>(x + (size_t)e3.x * D) + lane);
        acc_row(acc0, acc1, r0, __int_as_float(e0.y));
        acc_row(acc0, acc1, r1, __int_as_float(e1.y));
        acc_row(acc0, acc1, r2, __int_as_float(e2.y));
        acc_row(acc0, acc1, r3, __int_as_float(e3.y));
    }
    for (; e < end; e++) {
        int2 e0 = edge[e];
        uint4 r0 = __ldg(reinterpret_cast<const uint4*>(x + (size_t)e0.x * D) + lane);
        acc_row(acc0, acc1, r0, __int_as_float(e0.y));
    }

    acc0.x = fmaxf(acc0.x, 0.f); acc0.y = fmaxf(acc0.y, 0.f);
    acc0.z = fmaxf(acc0.z, 0.f); acc0.w = fmaxf(acc0.w, 0.f);
    acc1.x = fmaxf(acc1.x, 0.f); acc1.y = fmaxf(acc1.y, 0.f);
    acc1.z = fmaxf(acc1.z, 0.f); acc1.w = fmaxf(acc1.w, 0.f);

    float4* o = reinterpret_cast<float4*>(out + (size_t)warp * D) + lane * 2;
    o[0] = acc0;
    o[1] = acc1;
}

// ---------------------------------------------------------------------------
// Launcher: CSR build (side stream) overlapped with GEMM (main stream),
// joined before SpMM. Fork/join via events — capture-legal pattern.
// ---------------------------------------------------------------------------
extern "C" void kernel_launch(void* const* d_in, const int* in_sizes, int n_in,
                              void* d_out, int out_size)
{
    const float* inputs = (const float*)d_in[0];
    const float* W      = (const float*)d_in[1];
    const int*   esrc   = (const int*)  d_in[2];
    const int*   edst   = (const int*)  d_in[3];
    const float* evals  = (const float*)d_in[4];
    float*       out    = (float*)d_out;

    const int M = in_sizes[0] / D;     // 100000
    const int E = in_sizes[2];         // 3200000

    __half* xh;
    int2* edge;
    int *off, *cur, *bsum;
    cudaGetSymbolAddress((void**)&xh,   g_xh);
    cudaGetSymbolAddress((void**)&off,  g_off);
    cudaGetSymbolAddress((void**)&cur,  g_cur);
    cudaGetSymbolAddress((void**)&bsum, g_bsum);
    cudaGetSymbolAddress((void**)&edge, g_edge);

    // One-time host-side handle creation (no device work, no device memory;
    // identical device work is enqueued on every call).
    static cudaStream_t side = nullptr;
    static cudaEvent_t  ev_fork = nullptr, ev_join = nullptr;
    if (side == nullptr) {
        cudaStreamCreateWithFlags(&side, cudaStreamNonBlocking);
        cudaEventCreateWithFlags(&ev_fork, cudaEventDisableTiming);
        cudaEventCreateWithFlags(&ev_join, cudaEventDisableTiming);
    }

    const int nblocks_scan = (M + SCAN_BLK - 1) / SCAN_BLK;

    // ---- fork: side stream joins the (possibly capturing) origin stream ----
    cudaEventRecord(ev_fork, 0);
    cudaStreamWaitEvent(side, ev_fork, 0);

    // ---- CSR build on side stream ----
    cudaMemsetAsync(cur, 0, M * sizeof(int), side);
    hist_kernel<<<(E + 255) / 256, 256, 0, side>>>(edst, cur, E);
    scan1_kernel<<<nblocks_scan, SCAN_BLK, 0, side>>>(cur, off, bsum, M);
    scan2_kernel<<<1, SCAN_BLK, 0, side>>>(bsum, nblocks_scan);
    scan3_kernel<<<(M + 256) / 256, 256, 0, side>>>(off, bsum, cur, M, E);
    scatter_kernel<<<(E + 255) / 256, 256, 0, side>>>(esrc, edst, evals, cur, edge, E);
    cudaEventRecord(ev_join, side);

    // ---- GEMM on main stream (independent of CSR build) ----
    {
        dim3 grid((M + BM - 1) / BM, 256 / BN);
        gemm_tf32_kernel<<<grid, 256>>>(inputs, W, xh, M);
    }

    // ---- join, then SpMM ----
    cudaStreamWaitEvent(0, ev_join, 0);
    {
        long long threads = (long long)M * 32;
        int blocks = (int)((threads + 255) / 256);
        spmm_csr_kernel<<<blocks, 256>>>(off, edge, xh, out, M);
    }
}

// round 8
// speedup vs baseline: 5.3346x; 1.0816x over previous
#include <cuda_runtime.h>
#include <cuda_fp16.h>
#include <cstdint>

#define D 256
#define MAX_NODES 100000
#define MAX_EDGES 3200000
#define SCAN_BLK 1024

// ---- device scratch (static: allocation rules) ----
static __device__ __half g_ah[(size_t)MAX_NODES * D];   // inputs, fp16
static __device__ __half g_wt[D * D];                   // W transposed [n][k], fp16
static __device__ __half g_xh[(size_t)MAX_NODES * D];   // inputs @ W, fp16
static __device__ int    g_off[MAX_NODES + 1];          // CSR offsets
static __device__ int    g_cur[MAX_NODES];              // histogram / scatter cursor
static __device__ int    g_bsum[(MAX_NODES + SCAN_BLK - 1) / SCAN_BLK + 1];
static __device__ int2   g_edge[MAX_EDGES];             // packed (src, val) sorted by dst

// ---------------------------------------------------------------------------
// CSR build
// ---------------------------------------------------------------------------
__global__ __launch_bounds__(256) void hist_kernel(
    const int* __restrict__ edst, int* __restrict__ cnt, int E)
{
    int i = blockIdx.x * blockDim.x + threadIdx.x;
    if (i < E) atomicAdd(&cnt[edst[i]], 1);
}

__global__ __launch_bounds__(SCAN_BLK) void scan1_kernel(
    const int* __restrict__ cnt, int* __restrict__ off, int* __restrict__ bsum, int n)
{
    __shared__ int s[SCAN_BLK];
    int tid = threadIdx.x;
    int i = blockIdx.x * SCAN_BLK + tid;
    int v = (i < n) ? cnt[i] : 0;
    s[tid] = v;
    __syncthreads();
#pragma unroll
    for (int d = 1; d < SCAN_BLK; d <<= 1) {
        int t = (tid >= d) ? s[tid - d] : 0;
        __syncthreads();
        s[tid] += t;
        __syncthreads();
    }
    if (i < n) off[i] = s[tid] - v;
    if (tid == SCAN_BLK - 1) bsum[blockIdx.x] = s[tid];
}

__global__ __launch_bounds__(SCAN_BLK) void scan2_kernel(int* __restrict__ bsum, int nb)
{
    __shared__ int s[SCAN_BLK];
    int tid = threadIdx.x;
    int v = (tid < nb) ? bsum[tid] : 0;
    s[tid] = v;
    __syncthreads();
#pragma unroll
    for (int d = 1; d < SCAN_BLK; d <<= 1) {
        int t = (tid >= d) ? s[tid - d] : 0;
        __syncthreads();
        s[tid] += t;
        __syncthreads();
    }
    if (tid < nb) bsum[tid] = s[tid] - v;
}

__global__ __launch_bounds__(256) void scan3_kernel(
    int* __restrict__ off, const int* __restrict__ bsum, int* __restrict__ cur,
    int n, int E)
{
    int i = blockIdx.x * blockDim.x + threadIdx.x;
    if (i < n) {
        int o = off[i] + bsum[i / SCAN_BLK];
        off[i] = o;
        cur[i] = o;
    }
    if (i == n) off[n] = E;
}

__global__ __launch_bounds__(256) void scatter_kernel(
    const int* __restrict__ esrc, const int* __restrict__ edst,
    const float* __restrict__ evals, int* __restrict__ cur,
    int2* __restrict__ edge, int E)
{
    int i = blockIdx.x * blockDim.x + threadIdx.x;
    if (i < E) {
        int d = edst[i];
        int pos = atomicAdd(&cur[d], 1);
        edge[pos] = make_int2(esrc[i], __float_as_int(evals[i]));
    }
}

// ---------------------------------------------------------------------------
// Conversions
// ---------------------------------------------------------------------------
// inputs fp32 -> fp16, 4 floats per thread
__global__ __launch_bounds__(256) void convert_inputs_kernel(
    const float4* __restrict__ in, uint2* __restrict__ outh, int n4)
{
    int i = blockIdx.x * blockDim.x + threadIdx.x;
    if (i < n4) {
        float4 v = in[i];
        __half2 lo = __floats2half2_rn(v.x, v.y);
        __half2 hi = __floats2half2_rn(v.z, v.w);
        outh[i] = make_uint2(*reinterpret_cast<uint32_t*>(&lo),
                             *reinterpret_cast<uint32_t*>(&hi));
    }
}

// W[k][n] fp32 -> Wt[n][k] fp16, tiled transpose
__global__ __launch_bounds__(1024) void convert_w_kernel(
    const float* __restrict__ W, __half* __restrict__ Wt)
{
    __shared__ float tile[32][33];
    int bx = blockIdx.x * 32;     // n base
    int by = blockIdx.y * 32;     // k base
    int tx = threadIdx.x & 31;
    int ty = threadIdx.x >> 5;
    // read W[by+ty][bx+tx] (coalesced over n)
    tile[ty][tx] = W[(by + ty) * D + bx + tx];
    __syncthreads();
    // write Wt[bx+ty][by+tx] (coalesced over k)
    Wt[(bx + ty) * D + by + tx] = __float2half_rn(tile[tx][ty]);
}

// ---------------------------------------------------------------------------
// fp16 tensor-core GEMM: Xh[M,256] = Ah[M,256] @ Wt^T, fp16 in/out, fp32 accum
// CTA 128x128, 8 warps (4x2), warp tile 32x64, BK=32, cp.async double buffer
// mma.sync.aligned.m16n8k16.row.col.f32.f16.f16.f32
// smem strides: 40 halves/row -> fragment LDS conflict-free (20g+t mod 32)
// ---------------------------------------------------------------------------
#define BM 128
#define BN 128
#define BKH 32
#define S_H 40

__device__ __forceinline__ void cp_async16(uint32_t dst, const void* src, bool valid)
{
    int sz = valid ? 16 : 0;
    asm volatile("cp.async.ca.shared.global [%0], [%1], 16, %2;\n"
                 :: "r"(dst), "l"(src), "r"(sz));
}

__global__ __launch_bounds__(256, 2) void gemm_f16_kernel(
    const __half* __restrict__ A,   // [M][256] row-major
    const __half* __restrict__ Bt,  // [256 n][256 k] (W transposed)
    __half* __restrict__ C, int M)
{
    __shared__ __half As[2][BM * S_H];   // [m][k] rows of 32 halves, stride 40
    __shared__ __half Bs[2][BN * S_H];   // [n][k] rows of 32 halves, stride 40

    const int tid = threadIdx.x;
    const int lane = tid & 31;
    const int wid = tid >> 5;
    const int g = lane >> 2;
    const int t = lane & 3;
    const int warp_m = (wid >> 1) * 32;
    const int warp_n = (wid & 1) * 64;
    const int row0 = blockIdx.x * BM;
    const int col0 = blockIdx.y * BN;

    float c[2][8][4];
#pragma unroll
    for (int i = 0; i < 2; i++)
#pragma unroll
        for (int j = 0; j < 8; j++)
#pragma unroll
            for (int k = 0; k < 4; k++) c[i][j][k] = 0.f;

    uint32_t sA[2], sB[2];
    sA[0] = (uint32_t)__cvta_generic_to_shared(&As[0][0]);
    sA[1] = (uint32_t)__cvta_generic_to_shared(&As[1][0]);
    sB[0] = (uint32_t)__cvta_generic_to_shared(&Bs[0][0]);
    sB[1] = (uint32_t)__cvta_generic_to_shared(&Bs[1][0]);

    // staging: 128 rows x 32 halves (64 B) = 4 x 16B chunks per row; 512 chunks,
    // 2 per thread. f = tid*2+i: row = f>>2, chunk = (f&3)*8 halves.
    const int r0 = (tid * 2) >> 2;
    const int c0 = ((tid * 2) & 3) * 8;
    const int r1 = (tid * 2 + 1) >> 2;
    const int c1 = ((tid * 2 + 1) & 3) * 8;

#define LOAD_STAGE(stage, k0)                                                         \
    do {                                                                              \
        cp_async16(sA[stage] + (uint32_t)(r0 * S_H + c0) * 2,                         \
                   A + (size_t)(row0 + r0) * 256 + (k0) + c0, row0 + r0 < M);         \
        cp_async16(sA[stage] + (uint32_t)(r1 * S_H + c1) * 2,                         \
                   A + (size_t)(row0 + r1) * 256 + (k0) + c1, row0 + r1 < M);         \
        cp_async16(sB[stage] + (uint32_t)(r0 * S_H + c0) * 2,                         \
                   Bt + (size_t)(col0 + r0) * 256 + (k0) + c0, true);                 \
        cp_async16(sB[stage] + (uint32_t)(r1 * S_H + c1) * 2,                         \
                   Bt + (size_t)(col0 + r1) * 256 + (k0) + c1, true);                 \
        asm volatile("cp.async.commit_group;\n");                                     \
    } while (0)

    LOAD_STAGE(0, 0);
    asm volatile("cp.async.wait_group 0;\n");
    __syncthreads();

    for (int k0 = 0; k0 < 256; k0 += BKH) {
        const int cur = (k0 / BKH) & 1;
        const int nxt = cur ^ 1;
        const bool more = (k0 + BKH) < 256;
        if (more) LOAD_STAGE(nxt, k0 + BKH);

        const __half* as = &As[cur][0];
        const __half* bs = &Bs[cur][0];

#pragma unroll
        for (int ks = 0; ks < 2; ks++) {
            const int kl = ks * 16;
            uint32_t af[2][4];
            uint32_t bf[8][2];
#pragma unroll
            for (int mt = 0; mt < 2; mt++) {
                int mb = warp_m + mt * 16;
                af[mt][0] = *reinterpret_cast<const uint32_t*>(&as[(mb + g) * S_H + kl + 2 * t]);
                af[mt][1] = *reinterpret_cast<const uint32_t*>(&as[(mb + g + 8) * S_H + kl + 2 * t]);
                af[mt][2] = *reinterpret_cast<const uint32_t*>(&as[(mb + g) * S_H + kl + 2 * t + 8]);
                af[mt][3] = *reinterpret_cast<const uint32_t*>(&as[(mb + g + 8) * S_H + kl + 2 * t + 8]);
            }
#pragma unroll
            for (int nt = 0; nt < 8; nt++) {
                int nb = warp_n + nt * 8 + g;
                bf[nt][0] = *reinterpret_cast<const uint32_t*>(&bs[nb * S_H + kl + 2 * t]);
                bf[nt][1] = *reinterpret_cast<const uint32_t*>(&bs[nb * S_H + kl + 2 * t + 8]);
            }
#pragma unroll
            for (int mt = 0; mt < 2; mt++)
#pragma unroll
                for (int nt = 0; nt < 8; nt++) {
                    asm volatile(
                        "mma.sync.aligned.m16n8k16.row.col.f32.f16.f16.f32 "
                        "{%0,%1,%2,%3}, {%4,%5,%6,%7}, {%8,%9}, {%0,%1,%2,%3};"
                        : "+f"(c[mt][nt][0]), "+f"(c[mt][nt][1]),
                          "+f"(c[mt][nt][2]), "+f"(c[mt][nt][3])
                        : "r"(af[mt][0]), "r"(af[mt][1]), "r"(af[mt][2]), "r"(af[mt][3]),
                          "r"(bf[nt][0]), "r"(bf[nt][1]));
                }
        }

        if (more) asm volatile("cp.async.wait_group 0;\n");
        __syncthreads();
    }

    // epilogue: fp32 accum -> fp16 stores
#pragma unroll
    for (int mt = 0; mt < 2; mt++) {
        int r1g = row0 + warp_m + mt * 16 + g;
        int r2g = r1g + 8;
#pragma unroll
        for (int nt = 0; nt < 8; nt++) {
            int cc = col0 + warp_n + nt * 8 + t * 2;
            if (r1g < M)
                *reinterpret_cast<__half2*>(&C[(size_t)r1g * 256 + cc]) =
                    __floats2half2_rn(c[mt][nt][0], c[mt][nt][1]);
            if (r2g < M)
                *reinterpret_cast<__half2*>(&C[(size_t)r2g * 256 + cc]) =
                    __floats2half2_rn(c[mt][nt][2], c[mt][nt][3]);
        }
    }
#undef LOAD_STAGE
}

// ---------------------------------------------------------------------------
// SpMM-CSR: one warp per node; packed int2 edges; fp16 gather, fp32 accumulate,
// fused ReLU, single store.
// ---------------------------------------------------------------------------
__device__ __forceinline__ float2 h2f2(uint32_t packed)
{
    __half2 h = *reinterpret_cast<__half2*>(&packed);
    return __half22float2(h);
}

__device__ __forceinline__ void acc_row(
    float4& a0, float4& a1, uint4 r, float v)
{
    float2 f;
    f = h2f2(r.x);
    a0.x = fmaf(v, f.x, a0.x); a0.y = fmaf(v, f.y, a0.y);
    f = h2f2(r.y);
    a0.z = fmaf(v, f.x, a0.z); a0.w = fmaf(v, f.y, a0.w);
    f = h2f2(r.z);
    a1.x = fmaf(v, f.x, a1.x); a1.y = fmaf(v, f.y, a1.y);
    f = h2f2(r.w);
    a1.z = fmaf(v, f.x, a1.z); a1.w = fmaf(v, f.y, a1.w);
}

__global__ __launch_bounds__(256) void spmm_csr_kernel(
    const int* __restrict__ off, const int2* __restrict__ edge,
    const __half* __restrict__ x, float* __restrict__ out, int N)
{
    int warp = (blockIdx.x * blockDim.x + threadIdx.x) >> 5;
    int lane = threadIdx.x & 31;
    if (warp >= N) return;

    int beg = off[warp];
    int end = off[warp + 1];

    float4 acc0 = make_float4(0.f, 0.f, 0.f, 0.f);
    float4 acc1 = make_float4(0.f, 0.f, 0.f, 0.f);

    int e = beg;
    for (; e + 4 <= end; e += 4) {
        int2 e0 = edge[e],     e1 = edge[e + 1];
        int2 e2 = edge[e + 2], e3 = edge[e + 3];
        uint4 r0 = __ldg(reinterpret_cast<const uint4*>(x + (size_t)e0.x * D) + lane);
        uint4 r1 = __ldg(reinterpret_cast<const uint4*>(x + (size_t)e1.x * D) + lane);
        uint4 r2 = __ldg(reinterpret_cast<const uint4*>(x + (size_t)e2.x * D) + lane);
        uint4 r3 = __ldg(reinterpret_cast<const uint4*>(x + (size_t)e3.x * D) + lane);
        acc_row(acc0, acc1, r0, __int_as_float(e0.y));
        acc_row(acc0, acc1, r1, __int_as_float(e1.y));
        acc_row(acc0, acc1, r2, __int_as_float(e2.y));
        acc_row(acc0, acc1, r3, __int_as_float(e3.y));
    }
    for (; e < end; e++) {
        int2 e0 = edge[e];
        uint4 r0 = __ldg(reinterpret_cast<const uint4*>(x + (size_t)e0.x * D) + lane);
        acc_row(acc0, acc1, r0, __int_as_float(e0.y));
    }

    acc0.x = fmaxf(acc0.x, 0.f); acc0.y = fmaxf(acc0.y, 0.f);
    acc0.z = fmaxf(acc0.z, 0.f); acc0.w = fmaxf(acc0.w, 0.f);
    acc1.x = fmaxf(acc1.x, 0.f); acc1.y = fmaxf(acc1.y, 0.f);
    acc1.z = fmaxf(acc1.z, 0.f); acc1.w = fmaxf(acc1.w, 0.f);

    float4* o = reinterpret_cast<float4*>(out + (size_t)warp * D) + lane * 2;
    o[0] = acc0;
    o[1] = acc1;
}

// ---------------------------------------------------------------------------
// Launcher: CSR build on side stream overlapped with convert + fp16 GEMM
// on the main stream; join before SpMM.
// ---------------------------------------------------------------------------
extern "C" void kernel_launch(void* const* d_in, const int* in_sizes, int n_in,
                              void* d_out, int out_size)
{
    const float* inputs = (const float*)d_in[0];
    const float* W      = (const float*)d_in[1];
    const int*   esrc   = (const int*)  d_in[2];
    const int*   edst   = (const int*)  d_in[3];
    const float* evals  = (const float*)d_in[4];
    float*       out    = (float*)d_out;

    const int M = in_sizes[0] / D;     // 100000
    const int E = in_sizes[2];         // 3200000

    __half *ah, *wt, *xh;
    int2* edge;
    int *off, *cur, *bsum;
    cudaGetSymbolAddress((void**)&ah,   g_ah);
    cudaGetSymbolAddress((void**)&wt,   g_wt);
    cudaGetSymbolAddress((void**)&xh,   g_xh);
    cudaGetSymbolAddress((void**)&off,  g_off);
    cudaGetSymbolAddress((void**)&cur,  g_cur);
    cudaGetSymbolAddress((void**)&bsum, g_bsum);
    cudaGetSymbolAddress((void**)&edge, g_edge);

    static cudaStream_t side = nullptr;
    static cudaEvent_t  ev_fork = nullptr, ev_join = nullptr;
    if (side == nullptr) {
        cudaStreamCreateWithFlags(&side, cudaStreamNonBlocking);
        cudaEventCreateWithFlags(&ev_fork, cudaEventDisableTiming);
        cudaEventCreateWithFlags(&ev_join, cudaEventDisableTiming);
    }

    const int nblocks_scan = (M + SCAN_BLK - 1) / SCAN_BLK;

    // ---- fork ----
    cudaEventRecord(ev_fork, 0);
    cudaStreamWaitEvent(side, ev_fork, 0);

    // ---- CSR build on side stream ----
    cudaMemsetAsync(cur, 0, M * sizeof(int), side);
    hist_kernel<<<(E + 255) / 256, 256, 0, side>>>(edst, cur, E);
    scan1_kernel<<<nblocks_scan, SCAN_BLK, 0, side>>>(cur, off, bsum, M);
    scan2_kernel<<<1, SCAN_BLK, 0, side>>>(bsum, nblocks_scan);
    scan3_kernel<<<(M + 256) / 256, 256, 0, side>>>(off, bsum, cur, M, E);
    scatter_kernel<<<(E + 255) / 256, 256, 0, side>>>(esrc, edst, evals, cur, edge, E);
    cudaEventRecord(ev_join, side);

    // ---- main stream: convert then fp16 GEMM ----
    {
        int n4 = (M * D) / 4;
        convert_inputs_kernel<<<(n4 + 255) / 256, 256>>>(
            (const float4*)inputs, (uint2*)ah, n4);
        dim3 wgrid(D / 32, D / 32);
        convert_w_kernel<<<wgrid, 1024>>>(W, wt);
        dim3 grid((M + BM - 1) / BM, D / BN);
        gemm_f16_kernel<<<grid, 256>>>(ah, wt, xh, M);
    }

    // ---- join, then SpMM ----
    cudaStreamWaitEvent(0, ev_join, 0);
    {
        long long threads = (long long)M * 32;
        int blocks = (int)((threads + 255) / 256);
        spmm_csr_kernel<<<blocks, 256>>>(off, edge, xh, out, M);
    }
}

// round 9
// speedup vs baseline: 5.4946x; 1.0300x over previous
#include <cuda_runtime.h>
#include <cuda_fp16.h>
#include <cstdint>

#define D 256
#define MAX_NODES 100000
#define MAX_EDGES 3200000
#define SCAN_BLK 1024

// ---- device scratch (static: allocation rules) ----
static __device__ __half g_wt[D * D];                   // W transposed [n][k], fp16
static __device__ __half g_xh[(size_t)MAX_NODES * D];   // inputs @ W, fp16
static __device__ int    g_off[MAX_NODES + 1];          // CSR offsets
static __device__ int    g_cur[MAX_NODES];              // histogram / scatter cursor
static __device__ int    g_bsum[(MAX_NODES + SCAN_BLK - 1) / SCAN_BLK + 1];
static __device__ int2   g_edge[MAX_EDGES];             // packed (src, val) sorted by dst

// ---------------------------------------------------------------------------
// CSR build
// ---------------------------------------------------------------------------
__global__ __launch_bounds__(256) void hist_kernel(
    const int* __restrict__ edst, int* __restrict__ cnt, int E)
{
    int i = blockIdx.x * blockDim.x + threadIdx.x;
    int i4 = i * 4;
    if (i4 + 3 < E) {
        int4 v = *reinterpret_cast<const int4*>(edst + i4);
        atomicAdd(&cnt[v.x], 1);
        atomicAdd(&cnt[v.y], 1);
        atomicAdd(&cnt[v.z], 1);
        atomicAdd(&cnt[v.w], 1);
    } else {
        for (int e = i4; e < E; e++) atomicAdd(&cnt[edst[e]], 1);
    }
}

__global__ __launch_bounds__(SCAN_BLK) void scan1_kernel(
    const int* __restrict__ cnt, int* __restrict__ off, int* __restrict__ bsum, int n)
{
    __shared__ int s[SCAN_BLK];
    int tid = threadIdx.x;
    int i = blockIdx.x * SCAN_BLK + tid;
    int v = (i < n) ? cnt[i] : 0;
    s[tid] = v;
    __syncthreads();
#pragma unroll
    for (int d = 1; d < SCAN_BLK; d <<= 1) {
        int t = (tid >= d) ? s[tid - d] : 0;
        __syncthreads();
        s[tid] += t;
        __syncthreads();
    }
    if (i < n) off[i] = s[tid] - v;
    if (tid == SCAN_BLK - 1) bsum[blockIdx.x] = s[tid];
}

__global__ __launch_bounds__(SCAN_BLK) void scan2_kernel(int* __restrict__ bsum, int nb)
{
    __shared__ int s[SCAN_BLK];
    int tid = threadIdx.x;
    int v = (tid < nb) ? bsum[tid] : 0;
    s[tid] = v;
    __syncthreads();
#pragma unroll
    for (int d = 1; d < SCAN_BLK; d <<= 1) {
        int t = (tid >= d) ? s[tid - d] : 0;
        __syncthreads();
        s[tid] += t;
        __syncthreads();
    }
    if (tid < nb) bsum[tid] = s[tid] - v;
}

__global__ __launch_bounds__(256) void scan3_kernel(
    int* __restrict__ off, const int* __restrict__ bsum, int* __restrict__ cur,
    int n, int E)
{
    int i = blockIdx.x * blockDim.x + threadIdx.x;
    if (i < n) {
        int o = off[i] + bsum[i / SCAN_BLK];
        off[i] = o;
        cur[i] = o;
    }
    if (i == n) off[n] = E;
}

__global__ __launch_bounds__(256) void scatter_kernel(
    const int* __restrict__ esrc, const int* __restrict__ edst,
    const float* __restrict__ evals, int* __restrict__ cur,
    int2* __restrict__ edge, int E)
{
    int i = blockIdx.x * blockDim.x + threadIdx.x;
    if (i < E) {
        int d = edst[i];
        int pos = atomicAdd(&cur[d], 1);
        edge[pos] = make_int2(esrc[i], __float_as_int(evals[i]));
    }
}

// ---------------------------------------------------------------------------
// W[k][n] fp32 -> Wt[n][k] fp16, tiled transpose
// ---------------------------------------------------------------------------
__global__ __launch_bounds__(1024) void convert_w_kernel(
    const float* __restrict__ W, __half* __restrict__ Wt)
{
    __shared__ float tile[32][33];
    int bx = blockIdx.x * 32;     // n base
    int by = blockIdx.y * 32;     // k base
    int tx = threadIdx.x & 31;
    int ty = threadIdx.x >> 5;
    tile[ty][tx] = W[(by + ty) * D + bx + tx];
    __syncthreads();
    Wt[(bx + ty) * D + by + tx] = __float2half_rn(tile[tx][ty]);
}

// ---------------------------------------------------------------------------
// fp16 tensor-core GEMM with fused fp32->fp16 A conversion:
//   Xh[M,256] = fp16(A32[M,256]) @ Wt^T
// A path: LDG.128 fp32 -> cvt -> STS.128 fp16 (register double-buffered)
// B path: cp.async fp16 double buffer
// CTA 128x128, 8 warps (4x2), warp tile 32x64, BK=32
// mma.sync.aligned.m16n8k16.row.col.f32.f16.f16.f32
// ---------------------------------------------------------------------------
#define BM 128
#define BN 128
#define BKH 32
#define S_H 40

__device__ __forceinline__ void cp_async16(uint32_t dst, const void* src, bool valid)
{
    int sz = valid ? 16 : 0;
    asm volatile("cp.async.ca.shared.global [%0], [%1], 16, %2;\n"
                 :: "r"(dst), "l"(src), "r"(sz));
}

__global__ __launch_bounds__(256, 2) void gemm_f16_kernel(
    const float* __restrict__ A32,  // [M][256] fp32 row-major
    const __half* __restrict__ Bt,  // [256 n][256 k] fp16 (W transposed)
    __half* __restrict__ C, int M)
{
    __shared__ __half As[2][BM * S_H];   // [m][k] rows of 32 halves, stride 40
    __shared__ __half Bs[2][BN * S_H];   // [n][k] rows of 32 halves, stride 40

    const int tid = threadIdx.x;
    const int lane = tid & 31;
    const int wid = tid >> 5;
    const int g = lane >> 2;
    const int t = lane & 3;
    const int warp_m = (wid >> 1) * 32;
    const int warp_n = (wid & 1) * 64;
    const int row0 = blockIdx.x * BM;
    const int col0 = blockIdx.y * BN;

    float c[2][8][4];
#pragma unroll
    for (int i = 0; i < 2; i++)
#pragma unroll
        for (int j = 0; j < 8; j++)
#pragma unroll
            for (int k = 0; k < 4; k++) c[i][j][k] = 0.f;

    uint32_t sA[2], sB[2];
    sA[0] = (uint32_t)__cvta_generic_to_shared(&As[0][0]);
    sA[1] = (uint32_t)__cvta_generic_to_shared(&As[1][0]);
    sB[0] = (uint32_t)__cvta_generic_to_shared(&Bs[0][0]);
    sB[1] = (uint32_t)__cvta_generic_to_shared(&Bs[1][0]);

    // Each thread owns 2 chunks of 8 halves (16 B smem / 32 B gmem-fp32).
    // f = tid*2+i : row = f>>2 (0..127), chunk col = (f&3)*8 halves.
    const int r0 = (tid * 2) >> 2;
    const int c0 = ((tid * 2) & 3) * 8;
    const int r1 = (tid * 2 + 1) >> 2;
    const int c1 = ((tid * 2 + 1) & 3) * 8;
    const bool v0 = (row0 + r0) < M;
    const bool v1 = (row0 + r1) < M;

    float4 areg[2][2];   // staging: [chunk][2x float4] = 8 floats per chunk

#define LDG_A(k0)                                                                     \
    do {                                                                              \
        if (v0) {                                                                     \
            const float4* p = reinterpret_cast<const float4*>(                        \
                A32 + (size_t)(row0 + r0) * 256 + (k0) + c0);                         \
            areg[0][0] = p[0]; areg[0][1] = p[1];                                     \
        } else {                                                                      \
            areg[0][0] = areg[0][1] = make_float4(0.f, 0.f, 0.f, 0.f);                \
        }                                                                             \
        if (v1) {                                                                     \
            const float4* p = reinterpret_cast<const float4*>(                        \
                A32 + (size_t)(row0 + r1) * 256 + (k0) + c1);                         \
            areg[1][0] = p[0]; areg[1][1] = p[1];                                     \
        } else {                                                                      \
            areg[1][0] = areg[1][1] = make_float4(0.f, 0.f, 0.f, 0.f);                \
        }                                                                             \
    } while (0)

#define STS_A(stage)                                                                  \
    do {                                                                              \
        __half2 h0 = __floats2half2_rn(areg[0][0].x, areg[0][0].y);                   \
        __half2 h1 = __floats2half2_rn(areg[0][0].z, areg[0][0].w);                   \
        __half2 h2 = __floats2half2_rn(areg[0][1].x, areg[0][1].y);                   \
        __half2 h3 = __floats2half2_rn(areg[0][1].z, areg[0][1].w);                   \
        *reinterpret_cast<__half2*>(&As[stage][r0 * S_H + c0 + 0]) = h0;              \
        *reinterpret_cast<__half2*>(&As[stage][r0 * S_H + c0 + 2]) = h1;              \
        *reinterpret_cast<__half2*>(&As[stage][r0 * S_H + c0 + 4]) = h2;              \
        *reinterpret_cast<__half2*>(&As[stage][r0 * S_H + c0 + 6]) = h3;              \
        h0 = __floats2half2_rn(areg[1][0].x, areg[1][0].y);                           \
        h1 = __floats2half2_rn(areg[1][0].z, areg[1][0].w);                           \
        h2 = __floats2half2_rn(areg[1][1].x, areg[1][1].y);                           \
        h3 = __floats2half2_rn(areg[1][1].z, areg[1][1].w);                           \
        *reinterpret_cast<__half2*>(&As[stage][r1 * S_H + c1 + 0]) = h0;              \
        *reinterpret_cast<__half2*>(&As[stage][r1 * S_H + c1 + 2]) = h1;              \
        *reinterpret_cast<__half2*>(&As[stage][r1 * S_H + c1 + 4]) = h2;              \
        *reinterpret_cast<__half2*>(&As[stage][r1 * S_H + c1 + 6]) = h3;              \
    } while (0)

#define LOAD_B(stage, k0)                                                             \
    do {                                                                              \
        cp_async16(sB[stage] + (uint32_t)(r0 * S_H + c0) * 2,                         \
                   Bt + (size_t)(col0 + r0) * 256 + (k0) + c0, true);                 \
        cp_async16(sB[stage] + (uint32_t)(r1 * S_H + c1) * 2,                         \
                   Bt + (size_t)(col0 + r1) * 256 + (k0) + c1, true);                 \
        asm volatile("cp.async.commit_group;\n");                                     \
    } while (0)

    // prologue
    LDG_A(0);
    LOAD_B(0, 0);
    STS_A(0);
    asm volatile("cp.async.wait_group 0;\n");
    __syncthreads();

    for (int k0 = 0; k0 < 256; k0 += BKH) {
        const int cur = (k0 / BKH) & 1;
        const int nxt = cur ^ 1;
        const bool more = (k0 + BKH) < 256;
        if (more) {
            LOAD_B(nxt, k0 + BKH);
            LDG_A(k0 + BKH);
        }

        const __half* as = &As[cur][0];
        const __half* bs = &Bs[cur][0];

#pragma unroll
        for (int ks = 0; ks < 2; ks++) {
            const int kl = ks * 16;
            uint32_t af[2][4];
            uint32_t bf[8][2];
#pragma unroll
            for (int mt = 0; mt < 2; mt++) {
                int mb = warp_m + mt * 16;
                af[mt][0] = *reinterpret_cast<const uint32_t*>(&as[(mb + g) * S_H + kl + 2 * t]);
                af[mt][1] = *reinterpret_cast<const uint32_t*>(&as[(mb + g + 8) * S_H + kl + 2 * t]);
                af[mt][2] = *reinterpret_cast<const uint32_t*>(&as[(mb + g) * S_H + kl + 2 * t + 8]);
                af[mt][3] = *reinterpret_cast<const uint32_t*>(&as[(mb + g + 8) * S_H + kl + 2 * t + 8]);
            }
#pragma unroll
            for (int nt = 0; nt < 8; nt++) {
                int nb = warp_n + nt * 8 + g;
                bf[nt][0] = *reinterpret_cast<const uint32_t*>(&bs[nb * S_H + kl + 2 * t]);
                bf[nt][1] = *reinterpret_cast<const uint32_t*>(&bs[nb * S_H + kl + 2 * t + 8]);
            }
#pragma unroll
            for (int mt = 0; mt < 2; mt++)
#pragma unroll
                for (int nt = 0; nt < 8; nt++) {
                    asm volatile(
                        "mma.sync.aligned.m16n8k16.row.col.f32.f16.f16.f32 "
                        "{%0,%1,%2,%3}, {%4,%5,%6,%7}, {%8,%9}, {%0,%1,%2,%3};"
                        : "+f"(c[mt][nt][0]), "+f"(c[mt][nt][1]),
                          "+f"(c[mt][nt][2]), "+f"(c[mt][nt][3])
                        : "r"(af[mt][0]), "r"(af[mt][1]), "r"(af[mt][2]), "r"(af[mt][3]),
                          "r"(bf[nt][0]), "r"(bf[nt][1]));
                }
        }

        if (more) {
            STS_A(nxt);
            asm volatile("cp.async.wait_group 0;\n");
        }
        __syncthreads();
    }

    // epilogue
#pragma unroll
    for (int mt = 0; mt < 2; mt++) {
        int r1g = row0 + warp_m + mt * 16 + g;
        int r2g = r1g + 8;
#pragma unroll
        for (int nt = 0; nt < 8; nt++) {
            int cc = col0 + warp_n + nt * 8 + t * 2;
            if (r1g < M)
                *reinterpret_cast<__half2*>(&C[(size_t)r1g * 256 + cc]) =
                    __floats2half2_rn(c[mt][nt][0], c[mt][nt][1]);
            if (r2g < M)
                *reinterpret_cast<__half2*>(&C[(size_t)r2g * 256 + cc]) =
                    __floats2half2_rn(c[mt][nt][2], c[mt][nt][3]);
        }
    }
#undef LDG_A
#undef STS_A
#undef LOAD_B
}

// ---------------------------------------------------------------------------
// SpMM-CSR: one warp per node; packed int2 edges; fp16 gather, fp32 accumulate,
// fused ReLU, single store.
// ---------------------------------------------------------------------------
__device__ __forceinline__ float2 h2f2(uint32_t packed)
{
    __half2 h = *reinterpret_cast<__half2*>(&packed);
    return __half22float2(h);
}

__device__ __forceinline__ void acc_row(
    float4& a0, float4& a1, uint4 r, float v)
{
    float2 f;
    f = h2f2(r.x);
    a0.x = fmaf(v, f.x, a0.x); a0.y = fmaf(v, f.y, a0.y);
    f = h2f2(r.y);
    a0.z = fmaf(v, f.x, a0.z); a0.w = fmaf(v, f.y, a0.w);
    f = h2f2(r.z);
    a1.x = fmaf(v, f.x, a1.x); a1.y = fmaf(v, f.y, a1.y);
    f = h2f2(r.w);
    a1.z = fmaf(v, f.x, a1.z); a1.w = fmaf(v, f.y, a1.w);
}

__global__ __launch_bounds__(256) void spmm_csr_kernel(
    const int* __restrict__ off, const int2* __restrict__ edge,
    const __half* __restrict__ x, float* __restrict__ out, int N)
{
    int warp = (blockIdx.x * blockDim.x + threadIdx.x) >> 5;
    int lane = threadIdx.x & 31;
    if (warp >= N) return;

    int beg = off[warp];
    int end = off[warp + 1];

    float4 acc0 = make_float4(0.f, 0.f, 0.f, 0.f);
    float4 acc1 = make_float4(0.f, 0.f, 0.f, 0.f);

    int e = beg;
    for (; e + 4 <= end; e += 4) {
        int2 e0 = edge[e],     e1 = edge[e + 1];
        int2 e2 = edge[e + 2], e3 = edge[e + 3];
        uint4 r0 = __ldg(reinterpret_cast<const uint4*>(x + (size_t)e0.x * D) + lane);
        uint4 r1 = __ldg(reinterpret_cast<const uint4*>(x + (size_t)e1.x * D) + lane);
        uint4 r2 = __ldg(reinterpret_cast<const uint4*>(x + (size_t)e2.x * D) + lane);
        uint4 r3 = __ldg(reinterpret_cast<const uint4*>(x + (size_t)e3.x * D) + lane);
        acc_row(acc0, acc1, r0, __int_as_float(e0.y));
        acc_row(acc0, acc1, r1, __int_as_float(e1.y));
        acc_row(acc0, acc1, r2, __int_as_float(e2.y));
        acc_row(acc0, acc1, r3, __int_as_float(e3.y));
    }
    for (; e < end; e++) {
        int2 e0 = edge[e];
        uint4 r0 = __ldg(reinterpret_cast<const uint4*>(x + (size_t)e0.x * D) + lane);
        acc_row(acc0, acc1, r0, __int_as_float(e0.y));
    }

    acc0.x = fmaxf(acc0.x, 0.f); acc0.y = fmaxf(acc0.y, 0.f);
    acc0.z = fmaxf(acc0.z, 0.f); acc0.w = fmaxf(acc0.w, 0.f);
    acc1.x = fmaxf(acc1.x, 0.f); acc1.y = fmaxf(acc1.y, 0.f);
    acc1.w = fmaxf(acc1.w, 0.f); acc1.z = fmaxf(acc1.z, 0.f);

    float4* o = reinterpret_cast<float4*>(out + (size_t)warp * D) + lane * 2;
    o[0] = acc0;
    o[1] = acc1;
}

// ---------------------------------------------------------------------------
// Launcher: CSR build on side stream overlapped with convW + fused-convert
// fp16 GEMM on the main stream; join before SpMM.
// ---------------------------------------------------------------------------
extern "C" void kernel_launch(void* const* d_in, const int* in_sizes, int n_in,
                              void* d_out, int out_size)
{
    const float* inputs = (const float*)d_in[0];
    const float* W      = (const float*)d_in[1];
    const int*   esrc   = (const int*)  d_in[2];
    const int*   edst   = (const int*)  d_in[3];
    const float* evals  = (const float*)d_in[4];
    float*       out    = (float*)d_out;

    const int M = in_sizes[0] / D;     // 100000
    const int E = in_sizes[2];         // 3200000

    __half *wt, *xh;
    int2* edge;
    int *off, *cur, *bsum;
    cudaGetSymbolAddress((void**)&wt,   g_wt);
    cudaGetSymbolAddress((void**)&xh,   g_xh);
    cudaGetSymbolAddress((void**)&off,  g_off);
    cudaGetSymbolAddress((void**)&cur,  g_cur);
    cudaGetSymbolAddress((void**)&bsum, g_bsum);
    cudaGetSymbolAddress((void**)&edge, g_edge);

    static cudaStream_t side = nullptr;
    static cudaEvent_t  ev_fork = nullptr, ev_join = nullptr;
    if (side == nullptr) {
        cudaStreamCreateWithFlags(&side, cudaStreamNonBlocking);
        cudaEventCreateWithFlags(&ev_fork, cudaEventDisableTiming);
        cudaEventCreateWithFlags(&ev_join, cudaEventDisableTiming);
    }

    const int nblocks_scan = (M + SCAN_BLK - 1) / SCAN_BLK;

    // ---- fork ----
    cudaEventRecord(ev_fork, 0);
    cudaStreamWaitEvent(side, ev_fork, 0);

    // ---- CSR build on side stream ----
    cudaMemsetAsync(cur, 0, M * sizeof(int), side);
    hist_kernel<<<(E / 4 + 255) / 256, 256, 0, side>>>(edst, cur, E);
    scan1_kernel<<<nblocks_scan, SCAN_BLK, 0, side>>>(cur, off, bsum, M);
    scan2_kernel<<<1, SCAN_BLK, 0, side>>>(bsum, nblocks_scan);
    scan3_kernel<<<(M + 256) / 256, 256, 0, side>>>(off, bsum, cur, M, E);
    scatter_kernel<<<(E + 255) / 256, 256, 0, side>>>(esrc, edst, evals, cur, edge, E);
    cudaEventRecord(ev_join, side);

    // ---- main stream: convW, then fused-convert fp16 GEMM ----
    {
        dim3 wgrid(D / 32, D / 32);
        convert_w_kernel<<<wgrid, 1024>>>(W, wt);
        dim3 grid((M + BM - 1) / BM, D / BN);
        gemm_f16_kernel<<<grid, 256>>>(inputs, wt, xh, M);
    }

    // ---- join, then SpMM ----
    cudaStreamWaitEvent(0, ev_join, 0);
    {
        long long threads = (long long)M * 32;
        int blocks = (int)((threads + 255) / 256);
        spmm_csr_kernel<<<blocks, 256>>>(off, edge, xh, out, M);
    }
}